// round 10
// baseline (speedup 1.0000x reference)
#include <cuda_runtime.h>
#include <cuda_bf16.h>
#include <math.h>
#include <stdint.h>

// ---------------- problem constants ----------------
#define BATCH   2
#define TSEQ    512
#define NTOK    1024
#define DMODEL  1024
#define NHEADS  8
#define DKEY    128
#define HK      1024
#define NSUB    128
#define TOPK    16
#define HD      128
#define NZ      16        // BATCH*NHEADS

// ---------------- scratch ----------------
__device__ __align__(128) float g_q[NTOK * HK];          // BN'd q (fp32)
__device__ __align__(128) float g_qkv[NTOK * 3 * DMODEL];
__device__ __align__(128) float g_att[NZ * TSEQ * TSEQ];   // raw scores -> probs
__device__ __align__(128) float g_sum[NTOK * DMODEL];
__device__ __align__(128) float g_s[NTOK * NHEADS * 256];  // sub-key scores

__device__ __align__(128) __nv_bfloat16 g_x_hi[NTOK * DMODEL],  g_x_lo[NTOK * DMODEL];
__device__ __align__(128) __nv_bfloat16 g_w1_hi[4096 * DMODEL], g_w1_lo[4096 * DMODEL];
__device__ __align__(128) __nv_bfloat16 g_w2_hi[DMODEL * 2048], g_w2_lo[DMODEL * 2048];
__device__ __align__(128) __nv_bfloat16 g_cat_hi[NTOK * 2048],  g_cat_lo[NTOK * 2048];
__device__ __align__(128) __nv_bfloat16 g_qbn_hi[NTOK * HK],    g_qbn_lo[NTOK * HK];
__device__ __align__(128) __nv_bfloat16 g_bd_hi[256 * 128],     g_bd_lo[256 * 128];
__device__ __align__(128) __nv_bfloat16 g_qa_hi[NZ * TSEQ * HD], g_qa_lo[NZ * TSEQ * HD];
__device__ __align__(128) __nv_bfloat16 g_ka_hi[NZ * TSEQ * HD], g_ka_lo[NZ * TSEQ * HD];
__device__ __align__(128) __nv_bfloat16 g_p_hi[NZ * TSEQ * TSEQ], g_p_lo[NZ * TSEQ * TSEQ];
__device__ __align__(128) __nv_bfloat16 g_vt_hi[NZ * HD * TSEQ],  g_vt_lo[NZ * HD * TSEQ];

// 50 candidates (a,b) with (a+1)(b+1) <= 16 over rank-sorted v1,v2
__device__ const int CAND_A[50] = {0,0,0,0,0,0,0,0,0,0,0,0,0,0,0,0,
                                   1,1,1,1,1,1,1,1, 2,2,2,2,2, 3,3,3,3,
                                   4,4,4, 5,5, 6,6, 7,7, 8,9,10,11,12,13,14,15};
__device__ const int CAND_B[50] = {0,1,2,3,4,5,6,7,8,9,10,11,12,13,14,15,
                                   0,1,2,3,4,5,6,7, 0,1,2,3,4, 0,1,2,3,
                                   0,1,2, 0,1, 0,1, 0,1, 0,0,0,0,0,0,0,0};

// ---------------- helpers ----------------
__device__ __forceinline__ uint32_t smem_u32(const void* p) {
    uint32_t a;
    asm("{ .reg .u64 t; cvta.to.shared.u64 t, %1; cvt.u32.u64 %0, t; }"
        : "=r"(a) : "l"(p));
    return a;
}
#define LDSM4(r, addr) \
    asm volatile("ldmatrix.sync.aligned.m8n8.x4.shared.b16 {%0,%1,%2,%3}, [%4];" \
        : "=r"((r)[0]), "=r"((r)[1]), "=r"((r)[2]), "=r"((r)[3]) : "r"(addr))
#define MMA_BF16(d, a, b0, b1) \
    asm volatile("mma.sync.aligned.m16n8k16.row.col.f32.bf16.bf16.f32 " \
        "{%0,%1,%2,%3}, {%4,%5,%6,%7}, {%8,%9}, {%0,%1,%2,%3};" \
        : "+f"((d)[0]), "+f"((d)[1]), "+f"((d)[2]), "+f"((d)[3]) \
        : "r"((a)[0]), "r"((a)[1]), "r"((a)[2]), "r"((a)[3]), "r"(b0), "r"(b1))
#define CP16(dst, src) \
    asm volatile("cp.async.cg.shared.global [%0], [%1], 16;" :: "r"(dst), "l"(src))
#define CP_COMMIT() asm volatile("cp.async.commit_group;" ::: "memory")
#define CP_WAIT0()  asm volatile("cp.async.wait_group 0;" ::: "memory")

__device__ __forceinline__ void bf16x2_split_store(__nv_bfloat16* hi, __nv_bfloat16* lo,
                                                   size_t idx, float a, float b) {
    __nv_bfloat16 h0 = __float2bfloat16(a);
    __nv_bfloat16 h1 = __float2bfloat16(b);
    *(__nv_bfloat162*)(hi + idx) = __nv_bfloat162(h0, h1);
    *(__nv_bfloat162*)(lo + idx) = __nv_bfloat162(
        __float2bfloat16(a - __bfloat162float(h0)),
        __float2bfloat16(b - __bfloat162float(h1)));
}

// ============================================================================
// split kernels (fp32 -> bf16 hi/lo)
// ============================================================================
__device__ __forceinline__ void split_store4(float4 v, __nv_bfloat16* hi,
                                             __nv_bfloat16* lo, size_t i4) {
    float vv[4] = {v.x, v.y, v.z, v.w};
    __nv_bfloat16 h[4], l[4];
#pragma unroll
    for (int k = 0; k < 4; k++) {
        h[k] = __float2bfloat16(vv[k]);
        l[k] = __float2bfloat16(vv[k] - __bfloat162float(h[k]));
    }
    ((__nv_bfloat162*)hi)[2 * i4]     = __nv_bfloat162(h[0], h[1]);
    ((__nv_bfloat162*)hi)[2 * i4 + 1] = __nv_bfloat162(h[2], h[3]);
    ((__nv_bfloat162*)lo)[2 * i4]     = __nv_bfloat162(l[0], l[1]);
    ((__nv_bfloat162*)lo)[2 * i4 + 1] = __nv_bfloat162(l[2], l[3]);
}

#define X4   ((size_t)NTOK * DMODEL / 4)
#define W14  ((size_t)4096 * DMODEL / 4)
#define W24  ((size_t)DMODEL * 2048 / 4)
#define BD4  ((size_t)256 * 128 / 4)

__global__ void __launch_bounds__(256) split_x(const float* __restrict__ x) {
    size_t i = (size_t)blockIdx.x * 256 + threadIdx.x;
    split_store4(((const float4*)x)[i], g_x_hi, g_x_lo, i);
}
__global__ void __launch_bounds__(256) split_w1(const float* __restrict__ wq,
                                                const float* __restrict__ ipw) {
    size_t j = (size_t)blockIdx.x * 256 + threadIdx.x;
    const size_t cut = (size_t)1024 * 1024 / 4;
    float4 v = (j < cut) ? ((const float4*)wq)[j] : ((const float4*)ipw)[j - cut];
    split_store4(v, g_w1_hi, g_w1_lo, j);
}
__global__ void __launch_bounds__(256) split_w2bd(const float* __restrict__ wo,
                                                  const float* __restrict__ aow,
                                                  const float* __restrict__ sub_keys) {
    size_t i = (size_t)blockIdx.x * 256 + threadIdx.x;
    if (i < W24) {
        int row = (int)(i >> 9);
        int c4  = (int)(i & 511);
        float4 v = (c4 < 256) ? ((const float4*)wo)[row * 256 + c4]
                              : ((const float4*)aow)[row * 256 + c4 - 256];
        split_store4(v, g_w2_hi, g_w2_lo, i);
    } else if (i < W24 + BD4) {
        size_t j = i - W24;               // block-diag sub_keys (256 x 128)
        int row = (int)(j >> 5);
        int c4  = (int)(j & 31);
        float4 v = make_float4(0.f, 0.f, 0.f, 0.f);
        if (row < 128 && c4 < 16)
            v = ((const float4*)sub_keys)[row * 16 + c4];
        else if (row >= 128 && c4 >= 16)
            v = ((const float4*)(sub_keys + 128 * 64))[(row - 128) * 16 + (c4 - 16)];
        split_store4(v, g_bd_hi, g_bd_lo, j);
    }
}

// ============================================================================
// bf16-split "3M" GEMM (same as R9)
// ============================================================================
template<int MT>
__global__ void __launch_bounds__(256, 2) gemm_mma(
    const __nv_bfloat16* __restrict__ Ahi, const __nv_bfloat16* __restrict__ Alo,
    const __nv_bfloat16* __restrict__ Bhi, const __nv_bfloat16* __restrict__ Blo,
    int lda, int ldb, size_t batchA, size_t batchB,
    const float* __restrict__ biasA, const float* __restrict__ biasB,
    const float* __restrict__ bn_mean, const float* __restrict__ bn_var,
    const float* __restrict__ bn_w, const float* __restrict__ bn_b,
    int mode, float scale,
    float* __restrict__ C0, int ld0, float* __restrict__ C1, int ld1, int ncut,
    size_t batchC, int K)
{
    constexpr int CM   = 32 * MT;
    constexpr int A_T  = CM * 80;
    constexpr int B_T  = 128 * 80;
    constexpr int STG  = 2 * A_T + 2 * B_T;

    extern __shared__ char smc[];
    uint32_t base = smem_u32(smc);
    int t = threadIdx.x, warp = t >> 5, lane = t & 31;
    int m0 = blockIdx.y * CM, n0 = blockIdx.x * 128;
    int z  = blockIdx.z;
    int wm = warp >> 2, wn = warp & 3;

    const __nv_bfloat16* Ah = Ahi + batchA * z;
    const __nv_bfloat16* Al = Alo + batchA * z;
    const __nv_bfloat16* Bh = Bhi + batchB * z;
    const __nv_bfloat16* Bl = Blo + batchB * z;

    float acc[MT][4][4];
#pragma unroll
    for (int i = 0; i < MT; i++)
#pragma unroll
        for (int j = 0; j < 4; j++)
#pragma unroll
            for (int r = 0; r < 4; r++) acc[i][j][r] = 0.f;

    const int niter = K >> 5;

    auto issue = [&](int it) {
        uint32_t sb = base + (it & 1) * STG;
        int k0 = it << 5;
#pragma unroll
        for (int p = 0; p < CM / 64; p++) {
            int c = t + p * 256;
            int row = c >> 2, j = c & 3;
            const __nv_bfloat16* sh = Ah + (size_t)(m0 + row) * lda + k0 + j * 8;
            const __nv_bfloat16* sl = Al + (size_t)(m0 + row) * lda + k0 + j * 8;
            uint32_t d = sb + (uint32_t)(row * 80 + j * 16);
            CP16(d, sh);
            CP16(d + A_T, sl);
        }
#pragma unroll
        for (int p = 0; p < 2; p++) {
            int c = t + p * 256;
            int row = c >> 2, j = c & 3;
            const __nv_bfloat16* sh = Bh + (size_t)(n0 + row) * ldb + k0 + j * 8;
            const __nv_bfloat16* sl = Bl + (size_t)(n0 + row) * ldb + k0 + j * 8;
            uint32_t d = sb + 2 * A_T + (uint32_t)(row * 80 + j * 16);
            CP16(d, sh);
            CP16(d + B_T, sl);
        }
    };

    issue(0); CP_COMMIT();

    uint32_t a_off = (uint32_t)((wm * (16 * MT) + (lane & 15)) * 80 + (lane >> 4) * 16);
    uint32_t b_off = (uint32_t)((wn * 32 + (lane & 15)) * 80 + (lane >> 4) * 16);

    for (int it = 0; it < niter; ++it) {
        CP_WAIT0();
        __syncthreads();
        if (it + 1 < niter) { issue(it + 1); CP_COMMIT(); }

        uint32_t sb = base + (it & 1) * STG;
        uint32_t sa_h = sb, sa_l = sb + A_T;
        uint32_t sb_h = sb + 2 * A_T, sb_l = sb + 2 * A_T + B_T;

#pragma unroll
        for (int ks = 0; ks < 2; ks++) {
            uint32_t kb = ks * 32;
            uint32_t ah[MT][4], al[MT][4], bh[2][4], bl[2][4];
#pragma unroll
            for (int mt = 0; mt < MT; mt++) {
                uint32_t o = a_off + mt * 16 * 80 + kb;
                LDSM4(ah[mt], sa_h + o);
                LDSM4(al[mt], sa_l + o);
            }
#pragma unroll
            for (int bt = 0; bt < 2; bt++) {
                uint32_t o = b_off + bt * 16 * 80 + kb;
                LDSM4(bh[bt], sb_h + o);
                LDSM4(bl[bt], sb_l + o);
            }
#pragma unroll
            for (int mt = 0; mt < MT; mt++)
#pragma unroll
                for (int nt = 0; nt < 4; nt++)
                    MMA_BF16(acc[mt][nt], ah[mt], bh[nt >> 1][nt & 1], bh[nt >> 1][(nt & 1) + 2]);
#pragma unroll
            for (int mt = 0; mt < MT; mt++)
#pragma unroll
                for (int nt = 0; nt < 4; nt++)
                    MMA_BF16(acc[mt][nt], al[mt], bh[nt >> 1][nt & 1], bh[nt >> 1][(nt & 1) + 2]);
#pragma unroll
            for (int mt = 0; mt < MT; mt++)
#pragma unroll
                for (int nt = 0; nt < 4; nt++)
                    MMA_BF16(acc[mt][nt], ah[mt], bl[nt >> 1][nt & 1], bl[nt >> 1][(nt & 1) + 2]);
        }
    }

    // ---- epilogue ----
    int g = lane >> 2, c2 = lane & 3;
#pragma unroll
    for (int mt = 0; mt < MT; mt++) {
#pragma unroll
        for (int nt = 0; nt < 4; nt++) {
            int row = m0 + wm * (16 * MT) + mt * 16 + g;
            int col = n0 + wn * 32 + nt * 8 + 2 * c2;
            float v[4] = {acc[mt][nt][0], acc[mt][nt][1], acc[mt][nt][2], acc[mt][nt][3]};
            if (mode == 4) {
#pragma unroll
                for (int rr = 0; rr < 2; rr++) {
                    size_t idx = (size_t)((z >> 3) * 512 + row + rr * 8) * 2048
                               + 1024 + (z & 7) * 128 + col;
                    bf16x2_split_store(g_cat_hi, g_cat_lo, idx, v[2 * rr], v[2 * rr + 1]);
                }
                continue;
            }
            if (mode == 3) {
                v[0] *= scale; v[1] *= scale; v[2] *= scale; v[3] *= scale;
            } else if (mode == 0) {
                if (col < 1024) {
                    float sc0 = rsqrtf(bn_var[col] + 1e-5f) * bn_w[col];
                    float sc1 = rsqrtf(bn_var[col + 1] + 1e-5f) * bn_w[col + 1];
                    float of0 = (biasA[col] - bn_mean[col]) * sc0 + bn_b[col];
                    float of1 = (biasA[col + 1] - bn_mean[col + 1]) * sc1 + bn_b[col + 1];
                    v[0] = v[0] * sc0 + of0; v[1] = v[1] * sc1 + of1;
                    v[2] = v[2] * sc0 + of0; v[3] = v[3] * sc1 + of1;
#pragma unroll
                    for (int rr = 0; rr < 2; rr++)
                        bf16x2_split_store(g_qbn_hi, g_qbn_lo,
                                           (size_t)(row + rr * 8) * 1024 + col,
                                           v[2 * rr], v[2 * rr + 1]);
                } else {
                    float b0 = biasB[col - 1024], b1 = biasB[col + 1 - 1024];
                    v[0] += b0; v[1] += b1; v[2] += b0; v[3] += b1;
                    if (col < 3072) {
                        int cc   = (col < 2048) ? col - 1024 : col - 2048;
                        int h    = cc >> 7, d = cc & 127;
                        __nv_bfloat16* oh = (col < 2048) ? g_qa_hi : g_ka_hi;
                        __nv_bfloat16* ol = (col < 2048) ? g_qa_lo : g_ka_lo;
#pragma unroll
                        for (int rr = 0; rr < 2; rr++) {
                            int token = row + rr * 8;
                            int zz = (token >> 9) * 8 + h;
                            size_t idx = (size_t)zz * (TSEQ * HD)
                                       + (size_t)(token & 511) * HD + d;
                            bf16x2_split_store(oh, ol, idx, v[2 * rr], v[2 * rr + 1]);
                        }
                    }
                }
            } else if (mode == 1) {
                float b0 = biasA[col] + biasB[col];
                float b1 = biasA[col + 1] + biasB[col + 1];
                v[0] += b0; v[1] += b1; v[2] += b0; v[3] += b1;
            }
            float* C; int ld, cc;
            if (col < ncut) { C = C0; ld = ld0; cc = col; }
            else            { C = C1; ld = ld1; cc = col - ncut; }
            C += batchC * z;
            *(float2*)(C + (size_t)row * ld + cc)       = make_float2(v[0], v[1]);
            *(float2*)(C + (size_t)(row + 8) * ld + cc) = make_float2(v[2], v[3]);
        }
    }
}

// ============================================================================
// softmax over attention score rows
// ============================================================================
__global__ void __launch_bounds__(256) attn_softmax()
{
    int row = blockIdx.x;
    float* arow = g_att + (size_t)row * TSEQ;
    int t = threadIdx.x;
    float v0 = arow[t], v1 = arow[t + 256];

    __shared__ float red[8];
    float m = fmaxf(v0, v1);
#pragma unroll
    for (int off = 16; off; off >>= 1)
        m = fmaxf(m, __shfl_xor_sync(0xffffffffu, m, off));
    if ((t & 31) == 0) red[t >> 5] = m;
    __syncthreads();
    if (t < 32) {
        float mm = (t < 8) ? red[t] : -INFINITY;
#pragma unroll
        for (int off = 4; off; off >>= 1)
            mm = fmaxf(mm, __shfl_xor_sync(0xffffffffu, mm, off));
        if (t == 0) red[0] = mm;
    }
    __syncthreads();
    m = red[0];
    __syncthreads();

    float e0 = expf(v0 - m), e1 = expf(v1 - m);
    float s = e0 + e1;
#pragma unroll
    for (int off = 16; off; off >>= 1)
        s += __shfl_xor_sync(0xffffffffu, s, off);
    if ((t & 31) == 0) red[t >> 5] = s;
    __syncthreads();
    if (t < 32) {
        float ss = (t < 8) ? red[t] : 0.f;
#pragma unroll
        for (int off = 4; off; off >>= 1)
            ss += __shfl_xor_sync(0xffffffffu, ss, off);
        if (t == 0) red[0] = ss;
    }
    __syncthreads();
    float inv = 1.f / red[0];

    float p0 = e0 * inv, p1 = e1 * inv;
    arow[t] = p0; arow[t + 256] = p1;
    size_t base = (size_t)row * TSEQ;
    __nv_bfloat16 h0 = __float2bfloat16(p0);
    __nv_bfloat16 h1 = __float2bfloat16(p1);
    g_p_hi[base + t] = h0;       g_p_hi[base + t + 256] = h1;
    g_p_lo[base + t]       = __float2bfloat16(p0 - __bfloat162float(h0));
    g_p_lo[base + t + 256] = __float2bfloat16(p1 - __bfloat162float(h1));
}

// ============================================================================
// V transpose
// ============================================================================
__global__ void __launch_bounds__(256) v_transpose()
{
    int z = blockIdx.z;
    int b = z >> 3, h = z & 7;
    int k0 = blockIdx.x * 32, e0 = blockIdx.y * 32;
    __shared__ float tile[32][33];
    int tx = threadIdx.x & 31, ty = threadIdx.x >> 5;

#pragma unroll
    for (int s = 0; s < 4; s++) {
        int k = k0 + ty + s * 8;
        tile[ty + s * 8][tx] =
            g_qkv[(size_t)(b * TSEQ + k) * (3 * DMODEL) + 2 * DMODEL + h * HD + e0 + tx];
    }
    __syncthreads();
#pragma unroll
    for (int s = 0; s < 4; s++) {
        int e = e0 + ty + s * 8;
        float v = tile[tx][ty + s * 8];
        size_t idx = (size_t)z * (HD * TSEQ) + (size_t)e * TSEQ + k0 + tx;
        __nv_bfloat16 hh = __float2bfloat16(v);
        g_vt_hi[idx] = hh;
        g_vt_lo[idx] = __float2bfloat16(v - __bfloat162float(hh));
    }
}

// ============================================================================
// PEER routing: bitonic-sort top-16 (256 threads: 0-127 sort s1, 128-255 sort s2)
// ============================================================================
__global__ void __launch_bounds__(256) peer_route(const float* __restrict__ expert_w)
{
    int row   = blockIdx.x;
    int token = row >> 3;
    int head  = row & 7;
    int t     = threadIdx.x;
    int p     = t & 127;

    __shared__ float q[128];
    __shared__ float val1[128], val2[128];
    __shared__ int   idx1[128], idx2[128];
    __shared__ float cv[64];
    __shared__ int   ci[64];
    __shared__ int   sel[16];
    __shared__ float simv[16];
    __shared__ float rw[16];
    __shared__ float ews[16][128];

    if (t < 128) {
        q[t]    = g_q[(size_t)token * HK + head * 128 + t];
        val1[t] = g_s[(size_t)row * 256 + t];
        idx1[t] = t;
    } else {
        val2[p] = g_s[(size_t)row * 256 + 128 + p];
        idx2[p] = p;
    }
    __syncthreads();

    // bitonic sort both 128-element arrays (descending; idx asc tiebreak)
    float* V = (t < 128) ? val1 : val2;
    int*   I = (t < 128) ? idx1 : idx2;
#pragma unroll
    for (int k = 2; k <= 128; k <<= 1) {
#pragma unroll
        for (int j = k >> 1; j > 0; j >>= 1) {
            int q2 = p ^ j;
            if (q2 > p) {
                float va = V[p], vb = V[q2];
                int   ia = I[p], ib = I[q2];
                bool beforeAB = (va > vb) || (va == vb && ia < ib);
                bool doswap = ((p & k) == 0) ? !beforeAB : beforeAB;
                if (doswap) { V[p] = vb; V[q2] = va; I[p] = ib; I[q2] = ia; }
            }
            __syncthreads();
        }
    }

    // 50 dominance-pruned candidates; rank-select top 16
    if (t < 50) {
        int a = CAND_A[t], b = CAND_B[t];
        cv[t] = val1[a] + val2[b];
        ci[t] = idx1[a] * NSUB + idx2[b];
    }
    __syncthreads();
    if (t < 50) {
        float v = cv[t];
        int r = 0;
#pragma unroll 10
        for (int j = 0; j < 50; j++) {
            float w = cv[j];
            r += (w > v) || (w == v && j < t);
        }
        if (r < 16) sel[r] = ci[t];
    }
    __syncthreads();

    // gather 16 expert rows with 256 threads (2 rows at a time)
#pragma unroll
    for (int k = t >> 7; k < 16; k += 2)
        ews[k][p] = expert_w[(size_t)sel[k] * DKEY + p];
    __syncthreads();

    if (t < 128) {
        int k8 = t >> 3, l8 = t & 7;
        float part = 0.f;
#pragma unroll
        for (int i = 0; i < 16; i++) {
            int d = l8 * 16 + i;
            part += q[d] * ews[k8][d];
        }
        part += __shfl_down_sync(0xffffffffu, part, 4);
        part += __shfl_down_sync(0xffffffffu, part, 2);
        part += __shfl_down_sync(0xffffffffu, part, 1);
        if (l8 == 0) simv[k8] = part;
    }
    __syncthreads();

    if (t == 0) {
        float m = -INFINITY;
#pragma unroll
        for (int k = 0; k < 16; k++) m = fmaxf(m, simv[k]);
        float e[16]; float s = 0.f;
#pragma unroll
        for (int k = 0; k < 16; k++) { e[k] = expf(simv[k] - m); s += e[k]; }
        float inv = 1.f / s;
#pragma unroll
        for (int k = 0; k < 16; k++) rw[k] = e[k] * inv;
    }
    __syncthreads();

    if (t < 128) {
        float o = 0.f;
#pragma unroll
        for (int k = 0; k < 16; k++) o += rw[k] * ews[k][t];
        size_t idx = (size_t)token * 2048 + head * 128 + t;
        __nv_bfloat16 h = __float2bfloat16(o);
        g_cat_hi[idx] = h;
        g_cat_lo[idx] = __float2bfloat16(o - __bfloat162float(h));
    }
}

// mean over heads (float4)
__global__ void __launch_bounds__(256) attn_mean(float* __restrict__ out)
{
    int i4 = blockIdx.x * 256 + threadIdx.x;         // float4 index, 131072 total
    int b   = i4 / (TSEQ * TSEQ / 4);
    int rem = i4 - b * (TSEQ * TSEQ / 4);
    float4 s = make_float4(0.f, 0.f, 0.f, 0.f);
#pragma unroll
    for (int h = 0; h < 8; h++) {
        float4 v = ((const float4*)(g_att + ((size_t)(b * 8 + h)) * (TSEQ * TSEQ)))[rem];
        s.x += v.x; s.y += v.y; s.z += v.z; s.w += v.w;
    }
    s.x *= 0.125f; s.y *= 0.125f; s.z *= 0.125f; s.w *= 0.125f;
    ((float4*)out)[i4] = s;
}

// y = rmsnorm(x + g_sum) * rms_w
__global__ void __launch_bounds__(256) final_rms(
    const float* __restrict__ x, const float* __restrict__ rms_w,
    float* __restrict__ y)
{
    int token = blockIdx.x;
    int t = threadIdx.x;
    size_t base = (size_t)token * DMODEL;
    float v[4];
    float ss = 0.f;
#pragma unroll
    for (int u = 0; u < 4; u++) {
        int c = t + u * 256;
        float s = x[base + c] + g_sum[base + c];
        v[u] = s;
        ss += s * s;
    }
#pragma unroll
    for (int off = 16; off; off >>= 1)
        ss += __shfl_xor_sync(0xffffffffu, ss, off);
    __shared__ float red[8];
    __shared__ float stot;
    if ((t & 31) == 0) red[t >> 5] = ss;
    __syncthreads();
    if (t == 0) {
        float s = 0.f;
#pragma unroll
        for (int i = 0; i < 8; i++) s += red[i];
        stot = rsqrtf(s * (1.f / DMODEL) + 1e-6f);
    }
    __syncthreads();
    float inv = stot;
#pragma unroll
    for (int u = 0; u < 4; u++) {
        int c = t + u * 256;
        y[base + c] = v[u] * inv * rms_w[c];
    }
}

// ============================================================================
extern "C" void kernel_launch(void* const* d_in, const int* in_sizes, int n_in,
                              void* d_out, int out_size)
{
    const float* x         = (const float*)d_in[0];
    const float* wq        = (const float*)d_in[1];
    const float* bq        = (const float*)d_in[2];
    const float* bn_w      = (const float*)d_in[3];
    const float* bn_b      = (const float*)d_in[4];
    const float* bn_mean   = (const float*)d_in[5];
    const float* bn_var    = (const float*)d_in[6];
    const float* sub_keys  = (const float*)d_in[7];
    const float* expert_w  = (const float*)d_in[8];
    const float* wo        = (const float*)d_in[9];
    const float* bo        = (const float*)d_in[10];
    const float* in_proj_w = (const float*)d_in[11];
    const float* in_proj_b = (const float*)d_in[12];
    const float* attn_ow   = (const float*)d_in[13];
    const float* attn_ob   = (const float*)d_in[14];
    const float* rms_w     = (const float*)d_in[15];

    float* y      = (float*)d_out;
    float* attn_w = (float*)d_out + (size_t)NTOK * DMODEL;

    void *p_q, *p_qkv, *p_sum, *p_s, *p_att;
    cudaGetSymbolAddress(&p_q, g_q);
    cudaGetSymbolAddress(&p_qkv, g_qkv);
    cudaGetSymbolAddress(&p_sum, g_sum);
    cudaGetSymbolAddress(&p_s, g_s);
    cudaGetSymbolAddress(&p_att, g_att);

    void *xh, *xl, *w1h, *w1l, *w2h, *w2l, *ch, *cl, *qbh, *qbl, *bdh, *bdl;
    void *qah, *qal, *kah, *kal, *ph, *pl, *vth, *vtl;
    cudaGetSymbolAddress(&xh,  g_x_hi);  cudaGetSymbolAddress(&xl,  g_x_lo);
    cudaGetSymbolAddress(&w1h, g_w1_hi); cudaGetSymbolAddress(&w1l, g_w1_lo);
    cudaGetSymbolAddress(&w2h, g_w2_hi); cudaGetSymbolAddress(&w2l, g_w2_lo);
    cudaGetSymbolAddress(&ch,  g_cat_hi); cudaGetSymbolAddress(&cl, g_cat_lo);
    cudaGetSymbolAddress(&qbh, g_qbn_hi); cudaGetSymbolAddress(&qbl, g_qbn_lo);
    cudaGetSymbolAddress(&bdh, g_bd_hi); cudaGetSymbolAddress(&bdl, g_bd_lo);
    cudaGetSymbolAddress(&qah, g_qa_hi); cudaGetSymbolAddress(&qal, g_qa_lo);
    cudaGetSymbolAddress(&kah, g_ka_hi); cudaGetSymbolAddress(&kal, g_ka_lo);
    cudaGetSymbolAddress(&ph,  g_p_hi);  cudaGetSymbolAddress(&pl,  g_p_lo);
    cudaGetSymbolAddress(&vth, g_vt_hi); cudaGetSymbolAddress(&vtl, g_vt_lo);

    constexpr int SMEM4 = 2 * (2 * 128 * 80 + 2 * 128 * 80);  // 81920
    constexpr int SMEM2 = 2 * (2 * 64 * 80 + 2 * 128 * 80);   // 61440
    cudaFuncSetAttribute(gemm_mma<4>, cudaFuncAttributeMaxDynamicSharedMemorySize, SMEM4);
    cudaFuncSetAttribute(gemm_mma<2>, cudaFuncAttributeMaxDynamicSharedMemorySize, SMEM2);

    const float scale = 0.08838834764831845f;   // 1/sqrt(128)

    // [0..2] splits
    split_x  <<<(int)(X4 / 256), 256>>>(x);
    split_w1 <<<(int)(W14 / 256), 256>>>(wq, in_proj_w);
    split_w2bd<<<(int)((W24 + BD4) / 256), 256>>>(wo, attn_ow, sub_keys);

    // [3] fused q+qkv GEMM (mode 0)  <- ncu slot 3
    gemm_mma<4><<<dim3(4096 / 128, NTOK / 128), 256, SMEM4>>>(
        (const __nv_bfloat16*)xh, (const __nv_bfloat16*)xl,
        (const __nv_bfloat16*)w1h, (const __nv_bfloat16*)w1l,
        DMODEL, DMODEL, 0, 0,
        bq, in_proj_b, bn_mean, bn_var, bn_w, bn_b,
        0, 1.f,
        (float*)p_q, HK, (float*)p_qkv, 3 * DMODEL, 1024, 0, DMODEL);

    // [4] sub-key scores (mode 2)
    gemm_mma<4><<<dim3(2, 64), 256, SMEM4>>>(
        (const __nv_bfloat16*)qbh, (const __nv_bfloat16*)qbl,
        (const __nv_bfloat16*)bdh, (const __nv_bfloat16*)bdl,
        128, 128, 0, 0,
        nullptr, nullptr, nullptr, nullptr, nullptr, nullptr,
        2, 1.f,
        (float*)p_s, 256, (float*)p_s, 256, 1 << 30, 0, 128);

    // [5] QK^T batched GEMM (mode 3)
    gemm_mma<4><<<dim3(4, 4, NZ), 256, SMEM4>>>(
        (const __nv_bfloat16*)qah, (const __nv_bfloat16*)qal,
        (const __nv_bfloat16*)kah, (const __nv_bfloat16*)kal,
        HD, HD, (size_t)TSEQ * HD, (size_t)TSEQ * HD,
        nullptr, nullptr, nullptr, nullptr, nullptr, nullptr,
        3, scale,
        (float*)p_att, TSEQ, (float*)p_att, TSEQ, 1 << 30,
        (size_t)TSEQ * TSEQ, HD);

    // [6] softmax
    attn_softmax<<<NZ * TSEQ, 256>>>();

    // [7] V transpose
    v_transpose<<<dim3(TSEQ / 32, HD / 32, NZ), 256>>>();

    // [8] PEER routing (bitonic)
    peer_route<<<NTOK * NHEADS, 256>>>(expert_w);

    // [9] AV batched GEMM (mode 4)
    gemm_mma<2><<<dim3(1, 8, NZ), 256, SMEM2>>>(
        (const __nv_bfloat16*)ph, (const __nv_bfloat16*)pl,
        (const __nv_bfloat16*)vth, (const __nv_bfloat16*)vtl,
        TSEQ, TSEQ, (size_t)TSEQ * TSEQ, (size_t)HD * TSEQ,
        nullptr, nullptr, nullptr, nullptr, nullptr, nullptr,
        4, 1.f,
        nullptr, 0, nullptr, 0, 1 << 30, 0, TSEQ);

    // [10] attn_weights mean
    attn_mean<<<(BATCH * TSEQ * TSEQ / 4) / 256, 256>>>(attn_w);

    // [11] fused output projection (mode 1)
    gemm_mma<2><<<dim3(DMODEL / 128, NTOK / 64), 256, SMEM2>>>(
        (const __nv_bfloat16*)ch, (const __nv_bfloat16*)cl,
        (const __nv_bfloat16*)w2h, (const __nv_bfloat16*)w2l,
        2048, 2048, 0, 0,
        bo, attn_ob, nullptr, nullptr, nullptr, nullptr,
        1, 1.f,
        (float*)p_sum, DMODEL, (float*)p_sum, DMODEL, 1 << 30, 0, 2048);

    // [12] residual + rmsnorm
    final_rms<<<NTOK, 256>>>(x, rms_w, y);

    (void)in_sizes; (void)n_in; (void)out_size;
}

// round 11
// speedup vs baseline: 1.0078x; 1.0078x over previous
#include <cuda_runtime.h>
#include <cuda_bf16.h>
#include <math.h>
#include <stdint.h>

// ---------------- problem constants ----------------
#define BATCH   2
#define TSEQ    512
#define NTOK    1024
#define DMODEL  1024
#define NHEADS  8
#define DKEY    128
#define HK      1024
#define NSUB    128
#define TOPK    16
#define HD      128
#define NZ      16        // BATCH*NHEADS

// ---------------- scratch ----------------
__device__ __align__(128) float g_q[NTOK * HK];
__device__ __align__(128) float g_qkv[NTOK * 3 * DMODEL];
__device__ __align__(128) float g_att[NZ * TSEQ * TSEQ];
__device__ __align__(128) float g_sum[NTOK * DMODEL];
__device__ __align__(128) float g_s[NTOK * NHEADS * 256];

__device__ __align__(128) __nv_bfloat16 g_x_hi[NTOK * DMODEL],  g_x_lo[NTOK * DMODEL];
__device__ __align__(128) __nv_bfloat16 g_w1_hi[4096 * DMODEL], g_w1_lo[4096 * DMODEL];
__device__ __align__(128) __nv_bfloat16 g_w2_hi[DMODEL * 2048], g_w2_lo[DMODEL * 2048];
__device__ __align__(128) __nv_bfloat16 g_cat_hi[NTOK * 2048],  g_cat_lo[NTOK * 2048];
__device__ __align__(128) __nv_bfloat16 g_qbn_hi[NTOK * HK],    g_qbn_lo[NTOK * HK];
__device__ __align__(128) __nv_bfloat16 g_bd_hi[256 * 128],     g_bd_lo[256 * 128];
__device__ __align__(128) __nv_bfloat16 g_qa_hi[NZ * TSEQ * HD], g_qa_lo[NZ * TSEQ * HD];
__device__ __align__(128) __nv_bfloat16 g_ka_hi[NZ * TSEQ * HD], g_ka_lo[NZ * TSEQ * HD];
__device__ __align__(128) __nv_bfloat16 g_p_hi[NZ * TSEQ * TSEQ], g_p_lo[NZ * TSEQ * TSEQ];
__device__ __align__(128) __nv_bfloat16 g_vt_hi[NZ * HD * TSEQ],  g_vt_lo[NZ * HD * TSEQ];

// 50 candidates (a,b) with (a+1)(b+1) <= 16 over rank-sorted v1,v2
__device__ const int CAND_A[50] = {0,0,0,0,0,0,0,0,0,0,0,0,0,0,0,0,
                                   1,1,1,1,1,1,1,1, 2,2,2,2,2, 3,3,3,3,
                                   4,4,4, 5,5, 6,6, 7,7, 8,9,10,11,12,13,14,15};
__device__ const int CAND_B[50] = {0,1,2,3,4,5,6,7,8,9,10,11,12,13,14,15,
                                   0,1,2,3,4,5,6,7, 0,1,2,3,4, 0,1,2,3,
                                   0,1,2, 0,1, 0,1, 0,1, 0,0,0,0,0,0,0,0};

// ---------------- helpers ----------------
__device__ __forceinline__ uint32_t smem_u32(const void* p) {
    uint32_t a;
    asm("{ .reg .u64 t; cvta.to.shared.u64 t, %1; cvt.u32.u64 %0, t; }"
        : "=r"(a) : "l"(p));
    return a;
}
#define LDSM4(r, addr) \
    asm volatile("ldmatrix.sync.aligned.m8n8.x4.shared.b16 {%0,%1,%2,%3}, [%4];" \
        : "=r"((r)[0]), "=r"((r)[1]), "=r"((r)[2]), "=r"((r)[3]) : "r"(addr))
#define MMA_BF16(d, a, b0, b1) \
    asm volatile("mma.sync.aligned.m16n8k16.row.col.f32.bf16.bf16.f32 " \
        "{%0,%1,%2,%3}, {%4,%5,%6,%7}, {%8,%9}, {%0,%1,%2,%3};" \
        : "+f"((d)[0]), "+f"((d)[1]), "+f"((d)[2]), "+f"((d)[3]) \
        : "r"((a)[0]), "r"((a)[1]), "r"((a)[2]), "r"((a)[3]), "r"(b0), "r"(b1))
#define CP16(dst, src) \
    asm volatile("cp.async.cg.shared.global [%0], [%1], 16;" :: "r"(dst), "l"(src))
#define CP_COMMIT() asm volatile("cp.async.commit_group;" ::: "memory")
#define CP_WAIT0()  asm volatile("cp.async.wait_group 0;" ::: "memory")

__device__ __forceinline__ void bf16x2_split_store(__nv_bfloat16* hi, __nv_bfloat16* lo,
                                                   size_t idx, float a, float b) {
    __nv_bfloat16 h0 = __float2bfloat16(a);
    __nv_bfloat16 h1 = __float2bfloat16(b);
    *(__nv_bfloat162*)(hi + idx) = __nv_bfloat162(h0, h1);
    *(__nv_bfloat162*)(lo + idx) = __nv_bfloat162(
        __float2bfloat16(a - __bfloat162float(h0)),
        __float2bfloat16(b - __bfloat162float(h1)));
}

// ============================================================================
// combined split kernel
// ============================================================================
__device__ __forceinline__ void split_store4(float4 v, __nv_bfloat16* hi,
                                             __nv_bfloat16* lo, size_t i4) {
    float vv[4] = {v.x, v.y, v.z, v.w};
    __nv_bfloat16 h[4], l[4];
#pragma unroll
    for (int k = 0; k < 4; k++) {
        h[k] = __float2bfloat16(vv[k]);
        l[k] = __float2bfloat16(vv[k] - __bfloat162float(h[k]));
    }
    ((__nv_bfloat162*)hi)[2 * i4]     = __nv_bfloat162(h[0], h[1]);
    ((__nv_bfloat162*)hi)[2 * i4 + 1] = __nv_bfloat162(h[2], h[3]);
    ((__nv_bfloat162*)lo)[2 * i4]     = __nv_bfloat162(l[0], l[1]);
    ((__nv_bfloat162*)lo)[2 * i4 + 1] = __nv_bfloat162(l[2], l[3]);
}

#define X4   ((size_t)NTOK * DMODEL / 4)
#define W14  ((size_t)4096 * DMODEL / 4)
#define W24  ((size_t)DMODEL * 2048 / 4)
#define BD4  ((size_t)256 * 128 / 4)

__global__ void __launch_bounds__(256) split_all(
    const float* __restrict__ x,  const float* __restrict__ wq,
    const float* __restrict__ ipw, const float* __restrict__ wo,
    const float* __restrict__ aow, const float* __restrict__ sub_keys)
{
    size_t i = (size_t)blockIdx.x * 256 + threadIdx.x;
    if (i < X4) {
        split_store4(((const float4*)x)[i], g_x_hi, g_x_lo, i);
    } else if (i < X4 + W14) {
        size_t j = i - X4;
        const size_t cut = (size_t)1024 * 1024 / 4;
        float4 v = (j < cut) ? ((const float4*)wq)[j] : ((const float4*)ipw)[j - cut];
        split_store4(v, g_w1_hi, g_w1_lo, j);
    } else if (i < X4 + W14 + W24) {
        size_t j = i - X4 - W14;
        int row = (int)(j >> 9);
        int c4  = (int)(j & 511);
        float4 v = (c4 < 256) ? ((const float4*)wo)[row * 256 + c4]
                              : ((const float4*)aow)[row * 256 + c4 - 256];
        split_store4(v, g_w2_hi, g_w2_lo, j);
    } else {
        size_t j = i - X4 - W14 - W24;
        int row = (int)(j >> 5);
        int c4  = (int)(j & 31);
        float4 v = make_float4(0.f, 0.f, 0.f, 0.f);
        if (row < 128 && c4 < 16)
            v = ((const float4*)sub_keys)[row * 16 + c4];
        else if (row >= 128 && c4 >= 16)
            v = ((const float4*)(sub_keys + 128 * 64))[(row - 128) * 16 + (c4 - 16)];
        split_store4(v, g_bd_hi, g_bd_lo, j);
    }
}

// ============================================================================
// bf16-split "3M" GEMM (same as R9)
// ============================================================================
template<int MT>
__global__ void __launch_bounds__(256, 2) gemm_mma(
    const __nv_bfloat16* __restrict__ Ahi, const __nv_bfloat16* __restrict__ Alo,
    const __nv_bfloat16* __restrict__ Bhi, const __nv_bfloat16* __restrict__ Blo,
    int lda, int ldb, size_t batchA, size_t batchB,
    const float* __restrict__ biasA, const float* __restrict__ biasB,
    const float* __restrict__ bn_mean, const float* __restrict__ bn_var,
    const float* __restrict__ bn_w, const float* __restrict__ bn_b,
    int mode, float scale,
    float* __restrict__ C0, int ld0, float* __restrict__ C1, int ld1, int ncut,
    size_t batchC, int K)
{
    constexpr int CM   = 32 * MT;
    constexpr int A_T  = CM * 80;
    constexpr int B_T  = 128 * 80;
    constexpr int STG  = 2 * A_T + 2 * B_T;

    extern __shared__ char smc[];
    uint32_t base = smem_u32(smc);
    int t = threadIdx.x, warp = t >> 5, lane = t & 31;
    int m0 = blockIdx.y * CM, n0 = blockIdx.x * 128;
    int z  = blockIdx.z;
    int wm = warp >> 2, wn = warp & 3;

    const __nv_bfloat16* Ah = Ahi + batchA * z;
    const __nv_bfloat16* Al = Alo + batchA * z;
    const __nv_bfloat16* Bh = Bhi + batchB * z;
    const __nv_bfloat16* Bl = Blo + batchB * z;

    float acc[MT][4][4];
#pragma unroll
    for (int i = 0; i < MT; i++)
#pragma unroll
        for (int j = 0; j < 4; j++)
#pragma unroll
            for (int r = 0; r < 4; r++) acc[i][j][r] = 0.f;

    const int niter = K >> 5;

    auto issue = [&](int it) {
        uint32_t sb = base + (it & 1) * STG;
        int k0 = it << 5;
#pragma unroll
        for (int p = 0; p < CM / 64; p++) {
            int c = t + p * 256;
            int row = c >> 2, j = c & 3;
            const __nv_bfloat16* sh = Ah + (size_t)(m0 + row) * lda + k0 + j * 8;
            const __nv_bfloat16* sl = Al + (size_t)(m0 + row) * lda + k0 + j * 8;
            uint32_t d = sb + (uint32_t)(row * 80 + j * 16);
            CP16(d, sh);
            CP16(d + A_T, sl);
        }
#pragma unroll
        for (int p = 0; p < 2; p++) {
            int c = t + p * 256;
            int row = c >> 2, j = c & 3;
            const __nv_bfloat16* sh = Bh + (size_t)(n0 + row) * ldb + k0 + j * 8;
            const __nv_bfloat16* sl = Bl + (size_t)(n0 + row) * ldb + k0 + j * 8;
            uint32_t d = sb + 2 * A_T + (uint32_t)(row * 80 + j * 16);
            CP16(d, sh);
            CP16(d + B_T, sl);
        }
    };

    issue(0); CP_COMMIT();

    uint32_t a_off = (uint32_t)((wm * (16 * MT) + (lane & 15)) * 80 + (lane >> 4) * 16);
    uint32_t b_off = (uint32_t)((wn * 32 + (lane & 15)) * 80 + (lane >> 4) * 16);

    for (int it = 0; it < niter; ++it) {
        CP_WAIT0();
        __syncthreads();
        if (it + 1 < niter) { issue(it + 1); CP_COMMIT(); }

        uint32_t sb = base + (it & 1) * STG;
        uint32_t sa_h = sb, sa_l = sb + A_T;
        uint32_t sb_h = sb + 2 * A_T, sb_l = sb + 2 * A_T + B_T;

#pragma unroll
        for (int ks = 0; ks < 2; ks++) {
            uint32_t kb = ks * 32;
            uint32_t ah[MT][4], al[MT][4], bh[2][4], bl[2][4];
#pragma unroll
            for (int mt = 0; mt < MT; mt++) {
                uint32_t o = a_off + mt * 16 * 80 + kb;
                LDSM4(ah[mt], sa_h + o);
                LDSM4(al[mt], sa_l + o);
            }
#pragma unroll
            for (int bt = 0; bt < 2; bt++) {
                uint32_t o = b_off + bt * 16 * 80 + kb;
                LDSM4(bh[bt], sb_h + o);
                LDSM4(bl[bt], sb_l + o);
            }
#pragma unroll
            for (int mt = 0; mt < MT; mt++)
#pragma unroll
                for (int nt = 0; nt < 4; nt++)
                    MMA_BF16(acc[mt][nt], ah[mt], bh[nt >> 1][nt & 1], bh[nt >> 1][(nt & 1) + 2]);
#pragma unroll
            for (int mt = 0; mt < MT; mt++)
#pragma unroll
                for (int nt = 0; nt < 4; nt++)
                    MMA_BF16(acc[mt][nt], al[mt], bh[nt >> 1][nt & 1], bh[nt >> 1][(nt & 1) + 2]);
#pragma unroll
            for (int mt = 0; mt < MT; mt++)
#pragma unroll
                for (int nt = 0; nt < 4; nt++)
                    MMA_BF16(acc[mt][nt], ah[mt], bl[nt >> 1][nt & 1], bl[nt >> 1][(nt & 1) + 2]);
        }
    }

    // ---- epilogue ----
    int g = lane >> 2, c2 = lane & 3;
#pragma unroll
    for (int mt = 0; mt < MT; mt++) {
#pragma unroll
        for (int nt = 0; nt < 4; nt++) {
            int row = m0 + wm * (16 * MT) + mt * 16 + g;
            int col = n0 + wn * 32 + nt * 8 + 2 * c2;
            float v[4] = {acc[mt][nt][0], acc[mt][nt][1], acc[mt][nt][2], acc[mt][nt][3]};
            if (mode == 4) {
#pragma unroll
                for (int rr = 0; rr < 2; rr++) {
                    size_t idx = (size_t)((z >> 3) * 512 + row + rr * 8) * 2048
                               + 1024 + (z & 7) * 128 + col;
                    bf16x2_split_store(g_cat_hi, g_cat_lo, idx, v[2 * rr], v[2 * rr + 1]);
                }
                continue;
            }
            if (mode == 3) {
                v[0] *= scale; v[1] *= scale; v[2] *= scale; v[3] *= scale;
            } else if (mode == 0) {
                if (col < 1024) {
                    float sc0 = rsqrtf(bn_var[col] + 1e-5f) * bn_w[col];
                    float sc1 = rsqrtf(bn_var[col + 1] + 1e-5f) * bn_w[col + 1];
                    float of0 = (biasA[col] - bn_mean[col]) * sc0 + bn_b[col];
                    float of1 = (biasA[col + 1] - bn_mean[col + 1]) * sc1 + bn_b[col + 1];
                    v[0] = v[0] * sc0 + of0; v[1] = v[1] * sc1 + of1;
                    v[2] = v[2] * sc0 + of0; v[3] = v[3] * sc1 + of1;
#pragma unroll
                    for (int rr = 0; rr < 2; rr++)
                        bf16x2_split_store(g_qbn_hi, g_qbn_lo,
                                           (size_t)(row + rr * 8) * 1024 + col,
                                           v[2 * rr], v[2 * rr + 1]);
                } else {
                    float b0 = biasB[col - 1024], b1 = biasB[col + 1 - 1024];
                    v[0] += b0; v[1] += b1; v[2] += b0; v[3] += b1;
                    if (col < 3072) {
                        int cc   = (col < 2048) ? col - 1024 : col - 2048;
                        int h    = cc >> 7, d = cc & 127;
                        __nv_bfloat16* oh = (col < 2048) ? g_qa_hi : g_ka_hi;
                        __nv_bfloat16* ol = (col < 2048) ? g_qa_lo : g_ka_lo;
#pragma unroll
                        for (int rr = 0; rr < 2; rr++) {
                            int token = row + rr * 8;
                            int zz = (token >> 9) * 8 + h;
                            size_t idx = (size_t)zz * (TSEQ * HD)
                                       + (size_t)(token & 511) * HD + d;
                            bf16x2_split_store(oh, ol, idx, v[2 * rr], v[2 * rr + 1]);
                        }
                    }
                }
            } else if (mode == 1) {
                float b0 = biasA[col] + biasB[col];
                float b1 = biasA[col + 1] + biasB[col + 1];
                v[0] += b0; v[1] += b1; v[2] += b0; v[3] += b1;
            }
            float* C; int ld, cc;
            if (col < ncut) { C = C0; ld = ld0; cc = col; }
            else            { C = C1; ld = ld1; cc = col - ncut; }
            C += batchC * z;
            *(float2*)(C + (size_t)row * ld + cc)       = make_float2(v[0], v[1]);
            *(float2*)(C + (size_t)(row + 8) * ld + cc) = make_float2(v[2], v[3]);
        }
    }
}

// ============================================================================
// softmax over attention score rows
// ============================================================================
__global__ void __launch_bounds__(256) attn_softmax()
{
    int row = blockIdx.x;
    float* arow = g_att + (size_t)row * TSEQ;
    int t = threadIdx.x;
    float v0 = arow[t], v1 = arow[t + 256];

    __shared__ float red[8];
    float m = fmaxf(v0, v1);
#pragma unroll
    for (int off = 16; off; off >>= 1)
        m = fmaxf(m, __shfl_xor_sync(0xffffffffu, m, off));
    if ((t & 31) == 0) red[t >> 5] = m;
    __syncthreads();
    if (t < 32) {
        float mm = (t < 8) ? red[t] : -INFINITY;
#pragma unroll
        for (int off = 4; off; off >>= 1)
            mm = fmaxf(mm, __shfl_xor_sync(0xffffffffu, mm, off));
        if (t == 0) red[0] = mm;
    }
    __syncthreads();
    m = red[0];
    __syncthreads();

    float e0 = expf(v0 - m), e1 = expf(v1 - m);
    float s = e0 + e1;
#pragma unroll
    for (int off = 16; off; off >>= 1)
        s += __shfl_xor_sync(0xffffffffu, s, off);
    if ((t & 31) == 0) red[t >> 5] = s;
    __syncthreads();
    if (t < 32) {
        float ss = (t < 8) ? red[t] : 0.f;
#pragma unroll
        for (int off = 4; off; off >>= 1)
            ss += __shfl_xor_sync(0xffffffffu, ss, off);
        if (t == 0) red[0] = ss;
    }
    __syncthreads();
    float inv = 1.f / red[0];

    float p0 = e0 * inv, p1 = e1 * inv;
    arow[t] = p0; arow[t + 256] = p1;
    size_t base = (size_t)row * TSEQ;
    __nv_bfloat16 h0 = __float2bfloat16(p0);
    __nv_bfloat16 h1 = __float2bfloat16(p1);
    g_p_hi[base + t] = h0;       g_p_hi[base + t + 256] = h1;
    g_p_lo[base + t]       = __float2bfloat16(p0 - __bfloat162float(h0));
    g_p_lo[base + t + 256] = __float2bfloat16(p1 - __bfloat162float(h1));
}

// ============================================================================
// V transpose
// ============================================================================
__global__ void __launch_bounds__(256) v_transpose()
{
    int z = blockIdx.z;
    int b = z >> 3, h = z & 7;
    int k0 = blockIdx.x * 32, e0 = blockIdx.y * 32;
    __shared__ float tile[32][33];
    int tx = threadIdx.x & 31, ty = threadIdx.x >> 5;

#pragma unroll
    for (int s = 0; s < 4; s++) {
        int k = k0 + ty + s * 8;
        tile[ty + s * 8][tx] =
            g_qkv[(size_t)(b * TSEQ + k) * (3 * DMODEL) + 2 * DMODEL + h * HD + e0 + tx];
    }
    __syncthreads();
#pragma unroll
    for (int s = 0; s < 4; s++) {
        int e = e0 + ty + s * 8;
        float v = tile[tx][ty + s * 8];
        size_t idx = (size_t)z * (HD * TSEQ) + (size_t)e * TSEQ + k0 + tx;
        __nv_bfloat16 hh = __float2bfloat16(v);
        g_vt_hi[idx] = hh;
        g_vt_lo[idx] = __float2bfloat16(v - __bfloat162float(hh));
    }
}

// ============================================================================
// PEER routing: warp-level shfl bitonic top-16 (no block barriers in sort)
// 256 threads: warps 0-3 sort s1 chunks of 32, warps 4-7 sort s2 chunks.
// ============================================================================
__global__ void __launch_bounds__(256) peer_route(const float* __restrict__ expert_w)
{
    int row   = blockIdx.x;
    int token = row >> 3;
    int head  = row & 7;
    int t     = threadIdx.x;
    int lane  = t & 31, warp = t >> 5;

    __shared__ float q[128];
    __shared__ float c1v[64], c2v[64];
    __shared__ int   c1i[64], c2i[64];
    __shared__ float v1[16], v2[16];
    __shared__ int   i1[16], i2[16];
    __shared__ float cv[64];
    __shared__ int   ci[64];
    __shared__ int   sel[16];
    __shared__ float simv[16];
    __shared__ float rw[16];
    __shared__ float ews[16][128];

    if (t < 128) q[t] = g_q[(size_t)token * HK + head * 128 + t];

    // each warp loads 32 values of its array chunk and bitonic-sorts in registers
    int  wa     = warp & 3;
    bool second = warp >= 4;
    float v = g_s[(size_t)row * 256 + (second ? 128 : 0) + wa * 32 + lane];
    int   i = wa * 32 + lane;
#pragma unroll
    for (int k = 2; k <= 32; k <<= 1) {
#pragma unroll
        for (int j = k >> 1; j; j >>= 1) {
            float ov = __shfl_xor_sync(0xffffffffu, v, j);
            int   oi = __shfl_xor_sync(0xffffffffu, i, j);
            bool mine_first = (v > ov) || (v == ov && i < oi);
            bool low  = ((lane & j) == 0);
            bool desc = ((lane & k) == 0);
            if (mine_first != (low == desc)) { v = ov; i = oi; }
        }
    }
    if (lane < 16) {
        if (!second) { c1v[wa * 16 + lane] = v; c1i[wa * 16 + lane] = i; }
        else         { c2v[wa * 16 + lane] = v; c2i[wa * 16 + lane] = i; }
    }
    __syncthreads();

    // top-16 of each 64-candidate set via rank (threads 0-63: s1, 64-127: s2)
    if (t < 128) {
        const float* cc = (t < 64) ? c1v : c2v;
        const int*   cx = (t < 64) ? c1i : c2i;
        int p = t & 63;
        float vv = cc[p]; int ii = cx[p];
        int r = 0;
#pragma unroll 8
        for (int j = 0; j < 64; j++) {
            float w = cc[j];
            r += (w > vv) || (w == vv && cx[j] < ii);
        }
        if (r < 16) {
            if (t < 64) { v1[r] = vv; i1[r] = ii; }
            else        { v2[r] = vv; i2[r] = ii; }
        }
    }
    __syncthreads();

    // 50 dominance-pruned candidates; rank-select top 16
    if (t < 50) {
        int a = CAND_A[t], b = CAND_B[t];
        cv[t] = v1[a] + v2[b];
        ci[t] = i1[a] * NSUB + i2[b];
    }
    __syncthreads();
    if (t < 50) {
        float v5 = cv[t];
        int r = 0;
#pragma unroll 10
        for (int j = 0; j < 50; j++) {
            float w = cv[j];
            r += (w > v5) || (w == v5 && j < t);
        }
        if (r < 16) sel[r] = ci[t];
    }
    __syncthreads();

    // gather 16 expert rows with 256 threads (2 rows concurrently)
    int p = t & 127;
#pragma unroll
    for (int k = t >> 7; k < 16; k += 2)
        ews[k][p] = expert_w[(size_t)sel[k] * DKEY + p];
    __syncthreads();

    if (t < 128) {
        int k8 = t >> 3, l8 = t & 7;
        float part = 0.f;
#pragma unroll
        for (int ii2 = 0; ii2 < 16; ii2++) {
            int d = l8 * 16 + ii2;
            part += q[d] * ews[k8][d];
        }
        part += __shfl_down_sync(0xffffffffu, part, 4);
        part += __shfl_down_sync(0xffffffffu, part, 2);
        part += __shfl_down_sync(0xffffffffu, part, 1);
        if (l8 == 0) simv[k8] = part;
    }
    __syncthreads();

    if (t == 0) {
        float m = -INFINITY;
#pragma unroll
        for (int k = 0; k < 16; k++) m = fmaxf(m, simv[k]);
        float e[16]; float s = 0.f;
#pragma unroll
        for (int k = 0; k < 16; k++) { e[k] = expf(simv[k] - m); s += e[k]; }
        float inv = 1.f / s;
#pragma unroll
        for (int k = 0; k < 16; k++) rw[k] = e[k] * inv;
    }
    __syncthreads();

    if (t < 128) {
        float o = 0.f;
#pragma unroll
        for (int k = 0; k < 16; k++) o += rw[k] * ews[k][t];
        size_t idx = (size_t)token * 2048 + head * 128 + t;
        __nv_bfloat16 h = __float2bfloat16(o);
        g_cat_hi[idx] = h;
        g_cat_lo[idx] = __float2bfloat16(o - __bfloat162float(h));
    }
}

// mean over heads (float4)
__global__ void __launch_bounds__(256) attn_mean(float* __restrict__ out)
{
    int i4 = blockIdx.x * 256 + threadIdx.x;
    int b   = i4 / (TSEQ * TSEQ / 4);
    int rem = i4 - b * (TSEQ * TSEQ / 4);
    float4 s = make_float4(0.f, 0.f, 0.f, 0.f);
#pragma unroll
    for (int h = 0; h < 8; h++) {
        float4 v = ((const float4*)(g_att + ((size_t)(b * 8 + h)) * (TSEQ * TSEQ)))[rem];
        s.x += v.x; s.y += v.y; s.z += v.z; s.w += v.w;
    }
    s.x *= 0.125f; s.y *= 0.125f; s.z *= 0.125f; s.w *= 0.125f;
    ((float4*)out)[i4] = s;
}

// y = rmsnorm(x + g_sum) * rms_w
__global__ void __launch_bounds__(256) final_rms(
    const float* __restrict__ x, const float* __restrict__ rms_w,
    float* __restrict__ y)
{
    int token = blockIdx.x;
    int t = threadIdx.x;
    size_t base = (size_t)token * DMODEL;
    float v[4];
    float ss = 0.f;
#pragma unroll
    for (int u = 0; u < 4; u++) {
        int c = t + u * 256;
        float s = x[base + c] + g_sum[base + c];
        v[u] = s;
        ss += s * s;
    }
#pragma unroll
    for (int off = 16; off; off >>= 1)
        ss += __shfl_xor_sync(0xffffffffu, ss, off);
    __shared__ float red[8];
    __shared__ float stot;
    if ((t & 31) == 0) red[t >> 5] = ss;
    __syncthreads();
    if (t == 0) {
        float s = 0.f;
#pragma unroll
        for (int i = 0; i < 8; i++) s += red[i];
        stot = rsqrtf(s * (1.f / DMODEL) + 1e-6f);
    }
    __syncthreads();
    float inv = stot;
#pragma unroll
    for (int u = 0; u < 4; u++) {
        int c = t + u * 256;
        y[base + c] = v[u] * inv * rms_w[c];
    }
}

// ============================================================================
extern "C" void kernel_launch(void* const* d_in, const int* in_sizes, int n_in,
                              void* d_out, int out_size)
{
    const float* x         = (const float*)d_in[0];
    const float* wq        = (const float*)d_in[1];
    const float* bq        = (const float*)d_in[2];
    const float* bn_w      = (const float*)d_in[3];
    const float* bn_b      = (const float*)d_in[4];
    const float* bn_mean   = (const float*)d_in[5];
    const float* bn_var    = (const float*)d_in[6];
    const float* sub_keys  = (const float*)d_in[7];
    const float* expert_w  = (const float*)d_in[8];
    const float* wo        = (const float*)d_in[9];
    const float* bo        = (const float*)d_in[10];
    const float* in_proj_w = (const float*)d_in[11];
    const float* in_proj_b = (const float*)d_in[12];
    const float* attn_ow   = (const float*)d_in[13];
    const float* attn_ob   = (const float*)d_in[14];
    const float* rms_w     = (const float*)d_in[15];

    float* y      = (float*)d_out;
    float* attn_w = (float*)d_out + (size_t)NTOK * DMODEL;

    void *p_q, *p_qkv, *p_sum, *p_s, *p_att;
    cudaGetSymbolAddress(&p_q, g_q);
    cudaGetSymbolAddress(&p_qkv, g_qkv);
    cudaGetSymbolAddress(&p_sum, g_sum);
    cudaGetSymbolAddress(&p_s, g_s);
    cudaGetSymbolAddress(&p_att, g_att);

    void *xh, *xl, *w1h, *w1l, *w2h, *w2l, *ch, *cl, *qbh, *qbl, *bdh, *bdl;
    void *qah, *qal, *kah, *kal, *ph, *pl, *vth, *vtl;
    cudaGetSymbolAddress(&xh,  g_x_hi);  cudaGetSymbolAddress(&xl,  g_x_lo);
    cudaGetSymbolAddress(&w1h, g_w1_hi); cudaGetSymbolAddress(&w1l, g_w1_lo);
    cudaGetSymbolAddress(&w2h, g_w2_hi); cudaGetSymbolAddress(&w2l, g_w2_lo);
    cudaGetSymbolAddress(&ch,  g_cat_hi); cudaGetSymbolAddress(&cl, g_cat_lo);
    cudaGetSymbolAddress(&qbh, g_qbn_hi); cudaGetSymbolAddress(&qbl, g_qbn_lo);
    cudaGetSymbolAddress(&bdh, g_bd_hi); cudaGetSymbolAddress(&bdl, g_bd_lo);
    cudaGetSymbolAddress(&qah, g_qa_hi); cudaGetSymbolAddress(&qal, g_qa_lo);
    cudaGetSymbolAddress(&kah, g_ka_hi); cudaGetSymbolAddress(&kal, g_ka_lo);
    cudaGetSymbolAddress(&ph,  g_p_hi);  cudaGetSymbolAddress(&pl,  g_p_lo);
    cudaGetSymbolAddress(&vth, g_vt_hi); cudaGetSymbolAddress(&vtl, g_vt_lo);

    constexpr int SMEM4 = 2 * (2 * 128 * 80 + 2 * 128 * 80);  // 81920
    constexpr int SMEM2 = 2 * (2 * 64 * 80 + 2 * 128 * 80);   // 61440
    cudaFuncSetAttribute(gemm_mma<4>, cudaFuncAttributeMaxDynamicSharedMemorySize, SMEM4);
    cudaFuncSetAttribute(gemm_mma<2>, cudaFuncAttributeMaxDynamicSharedMemorySize, SMEM2);

    const float scale = 0.08838834764831845f;   // 1/sqrt(128)

    // [0] split
    split_all<<<(int)((X4 + W14 + W24 + BD4) / 256), 256>>>(
        x, wq, in_proj_w, wo, attn_ow, sub_keys);

    // [1] fused q+qkv GEMM (mode 0)
    gemm_mma<4><<<dim3(4096 / 128, NTOK / 128), 256, SMEM4>>>(
        (const __nv_bfloat16*)xh, (const __nv_bfloat16*)xl,
        (const __nv_bfloat16*)w1h, (const __nv_bfloat16*)w1l,
        DMODEL, DMODEL, 0, 0,
        bq, in_proj_b, bn_mean, bn_var, bn_w, bn_b,
        0, 1.f,
        (float*)p_q, HK, (float*)p_qkv, 3 * DMODEL, 1024, 0, DMODEL);

    // [2] sub-key scores (mode 2)
    gemm_mma<4><<<dim3(2, 64), 256, SMEM4>>>(
        (const __nv_bfloat16*)qbh, (const __nv_bfloat16*)qbl,
        (const __nv_bfloat16*)bdh, (const __nv_bfloat16*)bdl,
        128, 128, 0, 0,
        nullptr, nullptr, nullptr, nullptr, nullptr, nullptr,
        2, 1.f,
        (float*)p_s, 256, (float*)p_s, 256, 1 << 30, 0, 128);

    // [3] PEER routing (warp-shfl bitonic)   <- ncu slot 3
    peer_route<<<NTOK * NHEADS, 256>>>(expert_w);

    // [4] QK^T batched GEMM (mode 3)
    gemm_mma<4><<<dim3(4, 4, NZ), 256, SMEM4>>>(
        (const __nv_bfloat16*)qah, (const __nv_bfloat16*)qal,
        (const __nv_bfloat16*)kah, (const __nv_bfloat16*)kal,
        HD, HD, (size_t)TSEQ * HD, (size_t)TSEQ * HD,
        nullptr, nullptr, nullptr, nullptr, nullptr, nullptr,
        3, scale,
        (float*)p_att, TSEQ, (float*)p_att, TSEQ, 1 << 30,
        (size_t)TSEQ * TSEQ, HD);

    // [5] softmax
    attn_softmax<<<NZ * TSEQ, 256>>>();

    // [6] V transpose
    v_transpose<<<dim3(TSEQ / 32, HD / 32, NZ), 256>>>();

    // [7] AV batched GEMM (mode 4)
    gemm_mma<2><<<dim3(1, 8, NZ), 256, SMEM2>>>(
        (const __nv_bfloat16*)ph, (const __nv_bfloat16*)pl,
        (const __nv_bfloat16*)vth, (const __nv_bfloat16*)vtl,
        TSEQ, TSEQ, (size_t)TSEQ * TSEQ, (size_t)HD * TSEQ,
        nullptr, nullptr, nullptr, nullptr, nullptr, nullptr,
        4, 1.f,
        nullptr, 0, nullptr, 0, 1 << 30, 0, TSEQ);

    // [8] attn_weights mean
    attn_mean<<<(BATCH * TSEQ * TSEQ / 4) / 256, 256>>>(attn_w);

    // [9] fused output projection (mode 1)
    gemm_mma<2><<<dim3(DMODEL / 128, NTOK / 64), 256, SMEM2>>>(
        (const __nv_bfloat16*)ch, (const __nv_bfloat16*)cl,
        (const __nv_bfloat16*)w2h, (const __nv_bfloat16*)w2l,
        2048, 2048, 0, 0,
        bo, attn_ob, nullptr, nullptr, nullptr, nullptr,
        1, 1.f,
        (float*)p_sum, DMODEL, (float*)p_sum, DMODEL, 1 << 30, 0, 2048);

    // [10] residual + rmsnorm
    final_rms<<<NTOK, 256>>>(x, rms_w, y);

    (void)in_sizes; (void)n_in; (void)out_size;
}

// round 12
// speedup vs baseline: 1.0743x; 1.0660x over previous
#include <cuda_runtime.h>
#include <cuda_bf16.h>
#include <math.h>
#include <stdint.h>

// ---------------- problem constants ----------------
#define BATCH   2
#define TSEQ    512
#define NTOK    1024
#define DMODEL  1024
#define NHEADS  8
#define DKEY    128
#define HK      1024
#define NSUB    128
#define TOPK    16
#define HD      128
#define NZ      16        // BATCH*NHEADS

// ---------------- scratch ----------------
__device__ __align__(128) float g_qkv[NTOK * 3 * DMODEL];
__device__ __align__(128) float g_att[NZ * TSEQ * TSEQ];   // raw scores
__device__ __align__(128) float g_sum[NTOK * DMODEL];
__device__ __align__(128) float g_s[NTOK * NHEADS * 256];

__device__ __align__(128) __nv_bfloat16 g_x_hi[NTOK * DMODEL],  g_x_lo[NTOK * DMODEL];
__device__ __align__(128) __nv_bfloat16 g_w1_hi[4096 * DMODEL], g_w1_lo[4096 * DMODEL];
__device__ __align__(128) __nv_bfloat16 g_w2_hi[DMODEL * 2048], g_w2_lo[DMODEL * 2048];
__device__ __align__(128) __nv_bfloat16 g_cat_hi[NTOK * 2048],  g_cat_lo[NTOK * 2048];
__device__ __align__(128) __nv_bfloat16 g_qbn_hi[NTOK * HK],    g_qbn_lo[NTOK * HK];
__device__ __align__(128) __nv_bfloat16 g_bd_hi[256 * 128],     g_bd_lo[256 * 128];
__device__ __align__(128) __nv_bfloat16 g_qa_hi[NZ * TSEQ * HD], g_qa_lo[NZ * TSEQ * HD];
__device__ __align__(128) __nv_bfloat16 g_ka_hi[NZ * TSEQ * HD], g_ka_lo[NZ * TSEQ * HD];
__device__ __align__(128) __nv_bfloat16 g_p_hi[NZ * TSEQ * TSEQ], g_p_lo[NZ * TSEQ * TSEQ];
__device__ __align__(128) __nv_bfloat16 g_vt_hi[NZ * HD * TSEQ],  g_vt_lo[NZ * HD * TSEQ];

// 50 candidates (a,b) with (a+1)(b+1) <= 16 over rank-sorted v1,v2
__device__ const int CAND_A[50] = {0,0,0,0,0,0,0,0,0,0,0,0,0,0,0,0,
                                   1,1,1,1,1,1,1,1, 2,2,2,2,2, 3,3,3,3,
                                   4,4,4, 5,5, 6,6, 7,7, 8,9,10,11,12,13,14,15};
__device__ const int CAND_B[50] = {0,1,2,3,4,5,6,7,8,9,10,11,12,13,14,15,
                                   0,1,2,3,4,5,6,7, 0,1,2,3,4, 0,1,2,3,
                                   0,1,2, 0,1, 0,1, 0,1, 0,0,0,0,0,0,0,0};

// ---------------- helpers ----------------
__device__ __forceinline__ uint32_t smem_u32(const void* p) {
    uint32_t a;
    asm("{ .reg .u64 t; cvta.to.shared.u64 t, %1; cvt.u32.u64 %0, t; }"
        : "=r"(a) : "l"(p));
    return a;
}
#define LDSM4(r, addr) \
    asm volatile("ldmatrix.sync.aligned.m8n8.x4.shared.b16 {%0,%1,%2,%3}, [%4];" \
        : "=r"((r)[0]), "=r"((r)[1]), "=r"((r)[2]), "=r"((r)[3]) : "r"(addr))
#define MMA_BF16(d, a, b0, b1) \
    asm volatile("mma.sync.aligned.m16n8k16.row.col.f32.bf16.bf16.f32 " \
        "{%0,%1,%2,%3}, {%4,%5,%6,%7}, {%8,%9}, {%0,%1,%2,%3};" \
        : "+f"((d)[0]), "+f"((d)[1]), "+f"((d)[2]), "+f"((d)[3]) \
        : "r"((a)[0]), "r"((a)[1]), "r"((a)[2]), "r"((a)[3]), "r"(b0), "r"(b1))
#define CP16(dst, src) \
    asm volatile("cp.async.cg.shared.global [%0], [%1], 16;" :: "r"(dst), "l"(src))
#define CP_COMMIT() asm volatile("cp.async.commit_group;" ::: "memory")
#define CP_WAIT0()  asm volatile("cp.async.wait_group 0;" ::: "memory")

__device__ __forceinline__ void bf16x2_split_store(__nv_bfloat16* hi, __nv_bfloat16* lo,
                                                   size_t idx, float a, float b) {
    __nv_bfloat16 h0 = __float2bfloat16(a);
    __nv_bfloat16 h1 = __float2bfloat16(b);
    *(__nv_bfloat162*)(hi + idx) = __nv_bfloat162(h0, h1);
    *(__nv_bfloat162*)(lo + idx) = __nv_bfloat162(
        __float2bfloat16(a - __bfloat162float(h0)),
        __float2bfloat16(b - __bfloat162float(h1)));
}

// ============================================================================
// combined split kernel
// ============================================================================
__device__ __forceinline__ void split_store4(float4 v, __nv_bfloat16* hi,
                                             __nv_bfloat16* lo, size_t i4) {
    float vv[4] = {v.x, v.y, v.z, v.w};
    __nv_bfloat16 h[4], l[4];
#pragma unroll
    for (int k = 0; k < 4; k++) {
        h[k] = __float2bfloat16(vv[k]);
        l[k] = __float2bfloat16(vv[k] - __bfloat162float(h[k]));
    }
    ((__nv_bfloat162*)hi)[2 * i4]     = __nv_bfloat162(h[0], h[1]);
    ((__nv_bfloat162*)hi)[2 * i4 + 1] = __nv_bfloat162(h[2], h[3]);
    ((__nv_bfloat162*)lo)[2 * i4]     = __nv_bfloat162(l[0], l[1]);
    ((__nv_bfloat162*)lo)[2 * i4 + 1] = __nv_bfloat162(l[2], l[3]);
}

#define X4   ((size_t)NTOK * DMODEL / 4)
#define W14  ((size_t)4096 * DMODEL / 4)
#define W24  ((size_t)DMODEL * 2048 / 4)
#define BD4  ((size_t)256 * 128 / 4)

__global__ void __launch_bounds__(256) split_all(
    const float* __restrict__ x,  const float* __restrict__ wq,
    const float* __restrict__ ipw, const float* __restrict__ wo,
    const float* __restrict__ aow, const float* __restrict__ sub_keys)
{
    size_t i = (size_t)blockIdx.x * 256 + threadIdx.x;
    if (i < X4) {
        split_store4(((const float4*)x)[i], g_x_hi, g_x_lo, i);
    } else if (i < X4 + W14) {
        size_t j = i - X4;
        const size_t cut = (size_t)1024 * 1024 / 4;
        float4 v = (j < cut) ? ((const float4*)wq)[j] : ((const float4*)ipw)[j - cut];
        split_store4(v, g_w1_hi, g_w1_lo, j);
    } else if (i < X4 + W14 + W24) {
        size_t j = i - X4 - W14;
        int row = (int)(j >> 9);
        int c4  = (int)(j & 511);
        float4 v = (c4 < 256) ? ((const float4*)wo)[row * 256 + c4]
                              : ((const float4*)aow)[row * 256 + c4 - 256];
        split_store4(v, g_w2_hi, g_w2_lo, j);
    } else {
        size_t j = i - X4 - W14 - W24;
        int row = (int)(j >> 5);
        int c4  = (int)(j & 31);
        float4 v = make_float4(0.f, 0.f, 0.f, 0.f);
        if (row < 128 && c4 < 16)
            v = ((const float4*)sub_keys)[row * 16 + c4];
        else if (row >= 128 && c4 >= 16)
            v = ((const float4*)(sub_keys + 128 * 64))[(row - 128) * 16 + (c4 - 16)];
        split_store4(v, g_bd_hi, g_bd_lo, j);
    }
}

// ============================================================================
// bf16-split "3M" GEMM
// ============================================================================
template<int MT>
__global__ void __launch_bounds__(256, 2) gemm_mma(
    const __nv_bfloat16* __restrict__ Ahi, const __nv_bfloat16* __restrict__ Alo,
    const __nv_bfloat16* __restrict__ Bhi, const __nv_bfloat16* __restrict__ Blo,
    int lda, int ldb, size_t batchA, size_t batchB,
    const float* __restrict__ biasA, const float* __restrict__ biasB,
    const float* __restrict__ bn_mean, const float* __restrict__ bn_var,
    const float* __restrict__ bn_w, const float* __restrict__ bn_b,
    int mode, float scale,
    float* __restrict__ C0, int ld0, float* __restrict__ C1, int ld1, int ncut,
    size_t batchC, int K)
{
    constexpr int CM   = 32 * MT;
    constexpr int A_T  = CM * 80;
    constexpr int B_T  = 128 * 80;
    constexpr int STG  = 2 * A_T + 2 * B_T;

    extern __shared__ char smc[];
    uint32_t base = smem_u32(smc);
    int t = threadIdx.x, warp = t >> 5, lane = t & 31;
    int m0 = blockIdx.y * CM, n0 = blockIdx.x * 128;
    int z  = blockIdx.z;
    int wm = warp >> 2, wn = warp & 3;

    const __nv_bfloat16* Ah = Ahi + batchA * z;
    const __nv_bfloat16* Al = Alo + batchA * z;
    const __nv_bfloat16* Bh = Bhi + batchB * z;
    const __nv_bfloat16* Bl = Blo + batchB * z;

    float acc[MT][4][4];
#pragma unroll
    for (int i = 0; i < MT; i++)
#pragma unroll
        for (int j = 0; j < 4; j++)
#pragma unroll
            for (int r = 0; r < 4; r++) acc[i][j][r] = 0.f;

    const int niter = K >> 5;

    auto issue = [&](int it) {
        uint32_t sb = base + (it & 1) * STG;
        int k0 = it << 5;
#pragma unroll
        for (int p = 0; p < CM / 64; p++) {
            int c = t + p * 256;
            int row = c >> 2, j = c & 3;
            const __nv_bfloat16* sh = Ah + (size_t)(m0 + row) * lda + k0 + j * 8;
            const __nv_bfloat16* sl = Al + (size_t)(m0 + row) * lda + k0 + j * 8;
            uint32_t d = sb + (uint32_t)(row * 80 + j * 16);
            CP16(d, sh);
            CP16(d + A_T, sl);
        }
#pragma unroll
        for (int p = 0; p < 2; p++) {
            int c = t + p * 256;
            int row = c >> 2, j = c & 3;
            const __nv_bfloat16* sh = Bh + (size_t)(n0 + row) * ldb + k0 + j * 8;
            const __nv_bfloat16* sl = Bl + (size_t)(n0 + row) * ldb + k0 + j * 8;
            uint32_t d = sb + 2 * A_T + (uint32_t)(row * 80 + j * 16);
            CP16(d, sh);
            CP16(d + B_T, sl);
        }
    };

    issue(0); CP_COMMIT();

    uint32_t a_off = (uint32_t)((wm * (16 * MT) + (lane & 15)) * 80 + (lane >> 4) * 16);
    uint32_t b_off = (uint32_t)((wn * 32 + (lane & 15)) * 80 + (lane >> 4) * 16);

    for (int it = 0; it < niter; ++it) {
        CP_WAIT0();
        __syncthreads();
        if (it + 1 < niter) { issue(it + 1); CP_COMMIT(); }

        uint32_t sb = base + (it & 1) * STG;
        uint32_t sa_h = sb, sa_l = sb + A_T;
        uint32_t sb_h = sb + 2 * A_T, sb_l = sb + 2 * A_T + B_T;

#pragma unroll
        for (int ks = 0; ks < 2; ks++) {
            uint32_t kb = ks * 32;
            uint32_t ah[MT][4], al[MT][4], bh[2][4], bl[2][4];
#pragma unroll
            for (int mt = 0; mt < MT; mt++) {
                uint32_t o = a_off + mt * 16 * 80 + kb;
                LDSM4(ah[mt], sa_h + o);
                LDSM4(al[mt], sa_l + o);
            }
#pragma unroll
            for (int bt = 0; bt < 2; bt++) {
                uint32_t o = b_off + bt * 16 * 80 + kb;
                LDSM4(bh[bt], sb_h + o);
                LDSM4(bl[bt], sb_l + o);
            }
#pragma unroll
            for (int mt = 0; mt < MT; mt++)
#pragma unroll
                for (int nt = 0; nt < 4; nt++)
                    MMA_BF16(acc[mt][nt], ah[mt], bh[nt >> 1][nt & 1], bh[nt >> 1][(nt & 1) + 2]);
#pragma unroll
            for (int mt = 0; mt < MT; mt++)
#pragma unroll
                for (int nt = 0; nt < 4; nt++)
                    MMA_BF16(acc[mt][nt], al[mt], bh[nt >> 1][nt & 1], bh[nt >> 1][(nt & 1) + 2]);
#pragma unroll
            for (int mt = 0; mt < MT; mt++)
#pragma unroll
                for (int nt = 0; nt < 4; nt++)
                    MMA_BF16(acc[mt][nt], ah[mt], bl[nt >> 1][nt & 1], bl[nt >> 1][(nt & 1) + 2]);
        }
    }

    // ---- epilogue ----
    int g = lane >> 2, c2 = lane & 3;
#pragma unroll
    for (int mt = 0; mt < MT; mt++) {
#pragma unroll
        for (int nt = 0; nt < 4; nt++) {
            int row = m0 + wm * (16 * MT) + mt * 16 + g;
            int col = n0 + wn * 32 + nt * 8 + 2 * c2;
            float v[4] = {acc[mt][nt][0], acc[mt][nt][1], acc[mt][nt][2], acc[mt][nt][3]};
            if (mode == 4) {
#pragma unroll
                for (int rr = 0; rr < 2; rr++) {
                    size_t idx = (size_t)((z >> 3) * 512 + row + rr * 8) * 2048
                               + 1024 + (z & 7) * 128 + col;
                    bf16x2_split_store(g_cat_hi, g_cat_lo, idx, v[2 * rr], v[2 * rr + 1]);
                }
                continue;
            }
            if (mode == 3) {
                v[0] *= scale; v[1] *= scale; v[2] *= scale; v[3] *= scale;
            } else if (mode == 0) {
                if (col < 1024) {
                    // BN'd q -> bf16 hi/lo only (no fp32 store)
                    float sc0 = rsqrtf(bn_var[col] + 1e-5f) * bn_w[col];
                    float sc1 = rsqrtf(bn_var[col + 1] + 1e-5f) * bn_w[col + 1];
                    float of0 = (biasA[col] - bn_mean[col]) * sc0 + bn_b[col];
                    float of1 = (biasA[col + 1] - bn_mean[col + 1]) * sc1 + bn_b[col + 1];
                    v[0] = v[0] * sc0 + of0; v[1] = v[1] * sc1 + of1;
                    v[2] = v[2] * sc0 + of0; v[3] = v[3] * sc1 + of1;
#pragma unroll
                    for (int rr = 0; rr < 2; rr++)
                        bf16x2_split_store(g_qbn_hi, g_qbn_lo,
                                           (size_t)(row + rr * 8) * 1024 + col,
                                           v[2 * rr], v[2 * rr + 1]);
                    continue;
                }
                float b0 = biasB[col - 1024], b1 = biasB[col + 1 - 1024];
                v[0] += b0; v[1] += b1; v[2] += b0; v[3] += b1;
                if (col < 3072) {
                    int cc   = (col < 2048) ? col - 1024 : col - 2048;
                    int h    = cc >> 7, d = cc & 127;
                    __nv_bfloat16* oh = (col < 2048) ? g_qa_hi : g_ka_hi;
                    __nv_bfloat16* ol = (col < 2048) ? g_qa_lo : g_ka_lo;
#pragma unroll
                    for (int rr = 0; rr < 2; rr++) {
                        int token = row + rr * 8;
                        int zz = (token >> 9) * 8 + h;
                        size_t idx = (size_t)zz * (TSEQ * HD)
                                   + (size_t)(token & 511) * HD + d;
                        bf16x2_split_store(oh, ol, idx, v[2 * rr], v[2 * rr + 1]);
                    }
                }
            } else if (mode == 1) {
                float b0 = biasA[col] + biasB[col];
                float b1 = biasA[col + 1] + biasB[col + 1];
                v[0] += b0; v[1] += b1; v[2] += b0; v[3] += b1;
            }
            float* C; int ld, cc;
            if (col < ncut) { C = C0; ld = ld0; cc = col; }
            else            { C = C1; ld = ld1; cc = col - ncut; }
            C += batchC * z;
            *(float2*)(C + (size_t)row * ld + cc)       = make_float2(v[0], v[1]);
            *(float2*)(C + (size_t)(row + 8) * ld + cc) = make_float2(v[2], v[3]);
        }
    }
}

// ============================================================================
// fused softmax + head-mean + P bf16 split. Block = (b, q), 512 threads.
// 2 warps per head; probs staged in smem for the head-mean.
// ============================================================================
__global__ void __launch_bounds__(512) attn_softmax_mean(float* __restrict__ attn_w)
{
    int bq = blockIdx.x;                 // b*512 + q
    int b  = bq >> 9, qi = bq & 511;
    int t  = threadIdx.x;
    int g  = t >> 6;                     // head 0..7
    int u  = t & 63;                     // position group within head
    int w  = t >> 5;                     // warp 0..15

    __shared__ float sp[8][512];         // probs, 16 KB
    __shared__ float red[32];

    int z = b * 8 + g;
    const float* arow = g_att + ((size_t)z * TSEQ + qi) * TSEQ;

    float v[8];
    float mx = -INFINITY;
#pragma unroll
    for (int i = 0; i < 8; i++) {
        v[i] = arow[u + i * 64];
        mx = fmaxf(mx, v[i]);
    }
#pragma unroll
    for (int off = 16; off; off >>= 1)
        mx = fmaxf(mx, __shfl_xor_sync(0xffffffffu, mx, off));
    if ((t & 31) == 0) red[w] = mx;
    __syncthreads();
    float hm = fmaxf(red[2 * g], red[2 * g + 1]);

    float e[8], s = 0.f;
#pragma unroll
    for (int i = 0; i < 8; i++) { e[i] = expf(v[i] - hm); s += e[i]; }
#pragma unroll
    for (int off = 16; off; off >>= 1)
        s += __shfl_xor_sync(0xffffffffu, s, off);
    if ((t & 31) == 0) red[16 + w] = s;
    __syncthreads();
    float inv = 1.f / (red[16 + 2 * g] + red[16 + 2 * g + 1]);

    size_t pbase = ((size_t)z * TSEQ + qi) * TSEQ;
#pragma unroll
    for (int i = 0; i < 8; i++) {
        float p = e[i] * inv;
        int k = u + i * 64;
        sp[g][k] = p;
        __nv_bfloat16 h = __float2bfloat16(p);
        g_p_hi[pbase + k] = h;
        g_p_lo[pbase + k] = __float2bfloat16(p - __bfloat162float(h));
    }
    __syncthreads();

    // head mean: 512 threads, one k each
    float m8 = 0.f;
#pragma unroll
    for (int h = 0; h < 8; h++) m8 += sp[h][t];
    attn_w[(size_t)bq * TSEQ + t] = m8 * 0.125f;
}

// ============================================================================
// V transpose
// ============================================================================
__global__ void __launch_bounds__(256) v_transpose()
{
    int z = blockIdx.z;
    int b = z >> 3, h = z & 7;
    int k0 = blockIdx.x * 32, e0 = blockIdx.y * 32;
    __shared__ float tile[32][33];
    int tx = threadIdx.x & 31, ty = threadIdx.x >> 5;

#pragma unroll
    for (int s = 0; s < 4; s++) {
        int k = k0 + ty + s * 8;
        tile[ty + s * 8][tx] =
            g_qkv[(size_t)(b * TSEQ + k) * (3 * DMODEL) + 2 * DMODEL + h * HD + e0 + tx];
    }
    __syncthreads();
#pragma unroll
    for (int s = 0; s < 4; s++) {
        int e = e0 + ty + s * 8;
        float v = tile[tx][ty + s * 8];
        size_t idx = (size_t)z * (HD * TSEQ) + (size_t)e * TSEQ + k0 + tx;
        __nv_bfloat16 hh = __float2bfloat16(v);
        g_vt_hi[idx] = hh;
        g_vt_lo[idx] = __float2bfloat16(v - __bfloat162float(hh));
    }
}

// ============================================================================
// PEER routing (R9 measured-best version; q from qbn hi+lo)
// ============================================================================
__global__ void __launch_bounds__(128) peer_route(const float* __restrict__ expert_w)
{
    int row   = blockIdx.x;
    int token = row >> 3;
    int head  = row & 7;
    int tid   = threadIdx.x;

    __shared__ float q[128];
    __shared__ float sh1[128], sh2[128];
    __shared__ float v1[16], v2[16];
    __shared__ int   i1[16], i2[16];
    __shared__ float cv[50];
    __shared__ int   ci[50];
    __shared__ int   sel[16];
    __shared__ float simv[16];
    __shared__ float rw[16];
    __shared__ float ews[16][128];

    size_t qidx = (size_t)token * HK + head * 128 + tid;
    q[tid] = __bfloat162float(g_qbn_hi[qidx]) + __bfloat162float(g_qbn_lo[qidx]);
    float s1v = g_s[(size_t)row * 256 + tid];
    float s2v = g_s[(size_t)row * 256 + 128 + tid];
    sh1[tid] = s1v; sh2[tid] = s2v;
    __syncthreads();

    int r1 = 0, r2 = 0;
#pragma unroll 8
    for (int j = 0; j < 128; j++) {
        float w1 = sh1[j]; r1 += (w1 > s1v) || (w1 == s1v && j < tid);
        float w2 = sh2[j]; r2 += (w2 > s2v) || (w2 == s2v && j < tid);
    }
    if (r1 < 16) { v1[r1] = s1v; i1[r1] = tid; }
    if (r2 < 16) { v2[r2] = s2v; i2[r2] = tid; }
    __syncthreads();

    if (tid < 50) {
        int a = CAND_A[tid], b = CAND_B[tid];
        cv[tid] = v1[a] + v2[b];
        ci[tid] = i1[a] * NSUB + i2[b];
    }
    __syncthreads();
    if (tid < 50) {
        float v = cv[tid];
        int r = 0;
#pragma unroll 10
        for (int j = 0; j < 50; j++) {
            float w = cv[j];
            r += (w > v) || (w == v && j < tid);
        }
        if (r < 16) sel[r] = ci[tid];
    }
    __syncthreads();

#pragma unroll
    for (int k = 0; k < 16; k++)
        ews[k][tid] = expert_w[(size_t)sel[k] * DKEY + tid];
    __syncthreads();

    int k8 = tid >> 3, l8 = tid & 7;
    float part = 0.f;
#pragma unroll
    for (int i = 0; i < 16; i++) {
        int d = l8 * 16 + i;
        part += q[d] * ews[k8][d];
    }
    part += __shfl_down_sync(0xffffffffu, part, 4);
    part += __shfl_down_sync(0xffffffffu, part, 2);
    part += __shfl_down_sync(0xffffffffu, part, 1);
    if (l8 == 0) simv[k8] = part;
    __syncthreads();

    if (tid == 0) {
        float m = -INFINITY;
#pragma unroll
        for (int k = 0; k < 16; k++) m = fmaxf(m, simv[k]);
        float e[16]; float s = 0.f;
#pragma unroll
        for (int k = 0; k < 16; k++) { e[k] = expf(simv[k] - m); s += e[k]; }
        float inv = 1.f / s;
#pragma unroll
        for (int k = 0; k < 16; k++) rw[k] = e[k] * inv;
    }
    __syncthreads();

    float o = 0.f;
#pragma unroll
    for (int k = 0; k < 16; k++) o += rw[k] * ews[k][tid];
    size_t idx = (size_t)token * 2048 + head * 128 + tid;
    __nv_bfloat16 h = __float2bfloat16(o);
    g_cat_hi[idx] = h;
    g_cat_lo[idx] = __float2bfloat16(o - __bfloat162float(h));
}

// y = rmsnorm(x + g_sum) * rms_w
__global__ void __launch_bounds__(256) final_rms(
    const float* __restrict__ x, const float* __restrict__ rms_w,
    float* __restrict__ y)
{
    int token = blockIdx.x;
    int t = threadIdx.x;
    size_t base = (size_t)token * DMODEL;
    float v[4];
    float ss = 0.f;
#pragma unroll
    for (int u = 0; u < 4; u++) {
        int c = t + u * 256;
        float s = x[base + c] + g_sum[base + c];
        v[u] = s;
        ss += s * s;
    }
#pragma unroll
    for (int off = 16; off; off >>= 1)
        ss += __shfl_xor_sync(0xffffffffu, ss, off);
    __shared__ float red[8];
    __shared__ float stot;
    if ((t & 31) == 0) red[t >> 5] = ss;
    __syncthreads();
    if (t == 0) {
        float s = 0.f;
#pragma unroll
        for (int i = 0; i < 8; i++) s += red[i];
        stot = rsqrtf(s * (1.f / DMODEL) + 1e-6f);
    }
    __syncthreads();
    float inv = stot;
#pragma unroll
    for (int u = 0; u < 4; u++) {
        int c = t + u * 256;
        y[base + c] = v[u] * inv * rms_w[c];
    }
}

// ============================================================================
extern "C" void kernel_launch(void* const* d_in, const int* in_sizes, int n_in,
                              void* d_out, int out_size)
{
    const float* x         = (const float*)d_in[0];
    const float* wq        = (const float*)d_in[1];
    const float* bq        = (const float*)d_in[2];
    const float* bn_w      = (const float*)d_in[3];
    const float* bn_b      = (const float*)d_in[4];
    const float* bn_mean   = (const float*)d_in[5];
    const float* bn_var    = (const float*)d_in[6];
    const float* sub_keys  = (const float*)d_in[7];
    const float* expert_w  = (const float*)d_in[8];
    const float* wo        = (const float*)d_in[9];
    const float* bo        = (const float*)d_in[10];
    const float* in_proj_w = (const float*)d_in[11];
    const float* in_proj_b = (const float*)d_in[12];
    const float* attn_ow   = (const float*)d_in[13];
    const float* attn_ob   = (const float*)d_in[14];
    const float* rms_w     = (const float*)d_in[15];

    float* y      = (float*)d_out;
    float* attn_w = (float*)d_out + (size_t)NTOK * DMODEL;

    void *p_qkv, *p_sum, *p_s, *p_att;
    cudaGetSymbolAddress(&p_qkv, g_qkv);
    cudaGetSymbolAddress(&p_sum, g_sum);
    cudaGetSymbolAddress(&p_s, g_s);
    cudaGetSymbolAddress(&p_att, g_att);

    void *xh, *xl, *w1h, *w1l, *w2h, *w2l, *ch, *cl, *qbh, *qbl, *bdh, *bdl;
    void *qah, *qal, *kah, *kal, *ph, *pl, *vth, *vtl;
    cudaGetSymbolAddress(&xh,  g_x_hi);  cudaGetSymbolAddress(&xl,  g_x_lo);
    cudaGetSymbolAddress(&w1h, g_w1_hi); cudaGetSymbolAddress(&w1l, g_w1_lo);
    cudaGetSymbolAddress(&w2h, g_w2_hi); cudaGetSymbolAddress(&w2l, g_w2_lo);
    cudaGetSymbolAddress(&ch,  g_cat_hi); cudaGetSymbolAddress(&cl, g_cat_lo);
    cudaGetSymbolAddress(&qbh, g_qbn_hi); cudaGetSymbolAddress(&qbl, g_qbn_lo);
    cudaGetSymbolAddress(&bdh, g_bd_hi); cudaGetSymbolAddress(&bdl, g_bd_lo);
    cudaGetSymbolAddress(&qah, g_qa_hi); cudaGetSymbolAddress(&qal, g_qa_lo);
    cudaGetSymbolAddress(&kah, g_ka_hi); cudaGetSymbolAddress(&kal, g_ka_lo);
    cudaGetSymbolAddress(&ph,  g_p_hi);  cudaGetSymbolAddress(&pl,  g_p_lo);
    cudaGetSymbolAddress(&vth, g_vt_hi); cudaGetSymbolAddress(&vtl, g_vt_lo);

    constexpr int SMEM4 = 2 * (2 * 128 * 80 + 2 * 128 * 80);  // 81920
    constexpr int SMEM2 = 2 * (2 * 64 * 80 + 2 * 128 * 80);   // 61440
    cudaFuncSetAttribute(gemm_mma<4>, cudaFuncAttributeMaxDynamicSharedMemorySize, SMEM4);
    cudaFuncSetAttribute(gemm_mma<2>, cudaFuncAttributeMaxDynamicSharedMemorySize, SMEM2);

    const float scale = 0.08838834764831845f;   // 1/sqrt(128)

    // [0] split
    split_all<<<(int)((X4 + W14 + W24 + BD4) / 256), 256>>>(
        x, wq, in_proj_w, wo, attn_ow, sub_keys);

    // [1] fused q+qkv GEMM (mode 0)
    gemm_mma<4><<<dim3(4096 / 128, NTOK / 128), 256, SMEM4>>>(
        (const __nv_bfloat16*)xh, (const __nv_bfloat16*)xl,
        (const __nv_bfloat16*)w1h, (const __nv_bfloat16*)w1l,
        DMODEL, DMODEL, 0, 0,
        bq, in_proj_b, bn_mean, bn_var, bn_w, bn_b,
        0, 1.f,
        (float*)p_qkv, 3 * DMODEL, (float*)p_qkv, 3 * DMODEL, 1024, 0, DMODEL);

    // [2] QK^T batched GEMM (mode 3)
    gemm_mma<4><<<dim3(4, 4, NZ), 256, SMEM4>>>(
        (const __nv_bfloat16*)qah, (const __nv_bfloat16*)qal,
        (const __nv_bfloat16*)kah, (const __nv_bfloat16*)kal,
        HD, HD, (size_t)TSEQ * HD, (size_t)TSEQ * HD,
        nullptr, nullptr, nullptr, nullptr, nullptr, nullptr,
        3, scale,
        (float*)p_att, TSEQ, (float*)p_att, TSEQ, 1 << 30,
        (size_t)TSEQ * TSEQ, HD);

    // [3] fused softmax + mean + P split  <- ncu slot 3
    attn_softmax_mean<<<NTOK, 512>>>(attn_w);

    // [4] sub-key scores (mode 2)
    gemm_mma<4><<<dim3(2, 64), 256, SMEM4>>>(
        (const __nv_bfloat16*)qbh, (const __nv_bfloat16*)qbl,
        (const __nv_bfloat16*)bdh, (const __nv_bfloat16*)bdl,
        128, 128, 0, 0,
        nullptr, nullptr, nullptr, nullptr, nullptr, nullptr,
        2, 1.f,
        (float*)p_s, 256, (float*)p_s, 256, 1 << 30, 0, 128);

    // [5] PEER routing
    peer_route<<<NTOK * NHEADS, 128>>>(expert_w);

    // [6] V transpose
    v_transpose<<<dim3(TSEQ / 32, HD / 32, NZ), 256>>>();

    // [7] AV batched GEMM (mode 4)
    gemm_mma<2><<<dim3(1, 8, NZ), 256, SMEM2>>>(
        (const __nv_bfloat16*)ph, (const __nv_bfloat16*)pl,
        (const __nv_bfloat16*)vth, (const __nv_bfloat16*)vtl,
        TSEQ, TSEQ, (size_t)TSEQ * TSEQ, (size_t)HD * TSEQ,
        nullptr, nullptr, nullptr, nullptr, nullptr, nullptr,
        4, 1.f,
        nullptr, 0, nullptr, 0, 1 << 30, 0, TSEQ);

    // [8] fused output projection (mode 1)
    gemm_mma<2><<<dim3(DMODEL / 128, NTOK / 64), 256, SMEM2>>>(
        (const __nv_bfloat16*)ch, (const __nv_bfloat16*)cl,
        (const __nv_bfloat16*)w2h, (const __nv_bfloat16*)w2l,
        2048, 2048, 0, 0,
        bo, attn_ob, nullptr, nullptr, nullptr, nullptr,
        1, 1.f,
        (float*)p_sum, DMODEL, (float*)p_sum, DMODEL, 1 << 30, 0, 2048);

    // [9] residual + rmsnorm
    final_rms<<<NTOK, 256>>>(x, rms_w, y);

    (void)in_sizes; (void)n_in; (void)out_size;
}

// round 13
// speedup vs baseline: 1.0909x; 1.0154x over previous
#include <cuda_runtime.h>
#include <cuda_bf16.h>
#include <math.h>
#include <stdint.h>

// ---------------- problem constants ----------------
#define BATCH   2
#define TSEQ    512
#define NTOK    1024
#define DMODEL  1024
#define NHEADS  8
#define DKEY    128
#define HK      1024
#define NSUB    128
#define TOPK    16
#define HD      128
#define NZ      16        // BATCH*NHEADS

// ---------------- scratch ----------------
__device__ __align__(128) float g_qkv[NTOK * 3 * DMODEL];
__device__ __align__(128) float g_att[NZ * TSEQ * TSEQ];   // raw scores
__device__ __align__(128) float g_sum[2 * NTOK * DMODEL];  // split-K partials
__device__ __align__(128) float g_s[NTOK * NHEADS * 256];

__device__ __align__(128) __nv_bfloat16 g_x_hi[NTOK * DMODEL],  g_x_lo[NTOK * DMODEL];
__device__ __align__(128) __nv_bfloat16 g_w1_hi[4096 * DMODEL], g_w1_lo[4096 * DMODEL];
__device__ __align__(128) __nv_bfloat16 g_w2_hi[DMODEL * 2048], g_w2_lo[DMODEL * 2048];
__device__ __align__(128) __nv_bfloat16 g_cat_hi[NTOK * 2048],  g_cat_lo[NTOK * 2048];
__device__ __align__(128) __nv_bfloat16 g_qbn_hi[NTOK * HK],    g_qbn_lo[NTOK * HK];
__device__ __align__(128) __nv_bfloat16 g_bd_hi[256 * 128],     g_bd_lo[256 * 128];
__device__ __align__(128) __nv_bfloat16 g_qa_hi[NZ * TSEQ * HD], g_qa_lo[NZ * TSEQ * HD];
__device__ __align__(128) __nv_bfloat16 g_ka_hi[NZ * TSEQ * HD], g_ka_lo[NZ * TSEQ * HD];
__device__ __align__(128) __nv_bfloat16 g_p_hi[NZ * TSEQ * TSEQ], g_p_lo[NZ * TSEQ * TSEQ];
__device__ __align__(128) __nv_bfloat16 g_vt_hi[NZ * HD * TSEQ],  g_vt_lo[NZ * HD * TSEQ];

// 50 candidates (a,b) with (a+1)(b+1) <= 16 over rank-sorted v1,v2
__device__ const int CAND_A[50] = {0,0,0,0,0,0,0,0,0,0,0,0,0,0,0,0,
                                   1,1,1,1,1,1,1,1, 2,2,2,2,2, 3,3,3,3,
                                   4,4,4, 5,5, 6,6, 7,7, 8,9,10,11,12,13,14,15};
__device__ const int CAND_B[50] = {0,1,2,3,4,5,6,7,8,9,10,11,12,13,14,15,
                                   0,1,2,3,4,5,6,7, 0,1,2,3,4, 0,1,2,3,
                                   0,1,2, 0,1, 0,1, 0,1, 0,0,0,0,0,0,0,0};

// ---------------- helpers ----------------
__device__ __forceinline__ uint32_t smem_u32(const void* p) {
    uint32_t a;
    asm("{ .reg .u64 t; cvta.to.shared.u64 t, %1; cvt.u32.u64 %0, t; }"
        : "=r"(a) : "l"(p));
    return a;
}
#define LDSM4(r, addr) \
    asm volatile("ldmatrix.sync.aligned.m8n8.x4.shared.b16 {%0,%1,%2,%3}, [%4];" \
        : "=r"((r)[0]), "=r"((r)[1]), "=r"((r)[2]), "=r"((r)[3]) : "r"(addr))
#define MMA_BF16(d, a, b0, b1) \
    asm volatile("mma.sync.aligned.m16n8k16.row.col.f32.bf16.bf16.f32 " \
        "{%0,%1,%2,%3}, {%4,%5,%6,%7}, {%8,%9}, {%0,%1,%2,%3};" \
        : "+f"((d)[0]), "+f"((d)[1]), "+f"((d)[2]), "+f"((d)[3]) \
        : "r"((a)[0]), "r"((a)[1]), "r"((a)[2]), "r"((a)[3]), "r"(b0), "r"(b1))
#define CP16(dst, src) \
    asm volatile("cp.async.cg.shared.global [%0], [%1], 16;" :: "r"(dst), "l"(src))
#define CP_COMMIT() asm volatile("cp.async.commit_group;" ::: "memory")
#define CP_WAIT0()  asm volatile("cp.async.wait_group 0;" ::: "memory")

__device__ __forceinline__ void bf16x2_split_store(__nv_bfloat16* hi, __nv_bfloat16* lo,
                                                   size_t idx, float a, float b) {
    __nv_bfloat16 h0 = __float2bfloat16(a);
    __nv_bfloat16 h1 = __float2bfloat16(b);
    *(__nv_bfloat162*)(hi + idx) = __nv_bfloat162(h0, h1);
    *(__nv_bfloat162*)(lo + idx) = __nv_bfloat162(
        __float2bfloat16(a - __bfloat162float(h0)),
        __float2bfloat16(b - __bfloat162float(h1)));
}

// ============================================================================
// combined split kernel
// ============================================================================
__device__ __forceinline__ void split_store4(float4 v, __nv_bfloat16* hi,
                                             __nv_bfloat16* lo, size_t i4) {
    float vv[4] = {v.x, v.y, v.z, v.w};
    __nv_bfloat16 h[4], l[4];
#pragma unroll
    for (int k = 0; k < 4; k++) {
        h[k] = __float2bfloat16(vv[k]);
        l[k] = __float2bfloat16(vv[k] - __bfloat162float(h[k]));
    }
    ((__nv_bfloat162*)hi)[2 * i4]     = __nv_bfloat162(h[0], h[1]);
    ((__nv_bfloat162*)hi)[2 * i4 + 1] = __nv_bfloat162(h[2], h[3]);
    ((__nv_bfloat162*)lo)[2 * i4]     = __nv_bfloat162(l[0], l[1]);
    ((__nv_bfloat162*)lo)[2 * i4 + 1] = __nv_bfloat162(l[2], l[3]);
}

#define X4   ((size_t)NTOK * DMODEL / 4)
#define W14  ((size_t)4096 * DMODEL / 4)
#define W24  ((size_t)DMODEL * 2048 / 4)
#define BD4  ((size_t)256 * 128 / 4)

__global__ void __launch_bounds__(256) split_all(
    const float* __restrict__ x,  const float* __restrict__ wq,
    const float* __restrict__ ipw, const float* __restrict__ wo,
    const float* __restrict__ aow, const float* __restrict__ sub_keys)
{
    size_t i = (size_t)blockIdx.x * 256 + threadIdx.x;
    if (i < X4) {
        split_store4(((const float4*)x)[i], g_x_hi, g_x_lo, i);
    } else if (i < X4 + W14) {
        size_t j = i - X4;
        const size_t cut = (size_t)1024 * 1024 / 4;
        float4 v = (j < cut) ? ((const float4*)wq)[j] : ((const float4*)ipw)[j - cut];
        split_store4(v, g_w1_hi, g_w1_lo, j);
    } else if (i < X4 + W14 + W24) {
        size_t j = i - X4 - W14;
        int row = (int)(j >> 9);
        int c4  = (int)(j & 511);
        float4 v = (c4 < 256) ? ((const float4*)wo)[row * 256 + c4]
                              : ((const float4*)aow)[row * 256 + c4 - 256];
        split_store4(v, g_w2_hi, g_w2_lo, j);
    } else {
        size_t j = i - X4 - W14 - W24;
        int row = (int)(j >> 5);
        int c4  = (int)(j & 31);
        float4 v = make_float4(0.f, 0.f, 0.f, 0.f);
        if (row < 128 && c4 < 16)
            v = ((const float4*)sub_keys)[row * 16 + c4];
        else if (row >= 128 && c4 >= 16)
            v = ((const float4*)(sub_keys + 128 * 64))[(row - 128) * 16 + (c4 - 16)];
        split_store4(v, g_bd_hi, g_bd_lo, j);
    }
}

// ============================================================================
// bf16-split "3M" GEMM
// mode 1: + (biasA+biasB) but only on batch z==0 (split-K partials)
// ============================================================================
template<int MT>
__global__ void __launch_bounds__(256, 2) gemm_mma(
    const __nv_bfloat16* __restrict__ Ahi, const __nv_bfloat16* __restrict__ Alo,
    const __nv_bfloat16* __restrict__ Bhi, const __nv_bfloat16* __restrict__ Blo,
    int lda, int ldb, size_t batchA, size_t batchB,
    const float* __restrict__ biasA, const float* __restrict__ biasB,
    const float* __restrict__ bn_mean, const float* __restrict__ bn_var,
    const float* __restrict__ bn_w, const float* __restrict__ bn_b,
    int mode, float scale,
    float* __restrict__ C0, int ld0, float* __restrict__ C1, int ld1, int ncut,
    size_t batchC, int K)
{
    constexpr int CM   = 32 * MT;
    constexpr int A_T  = CM * 80;
    constexpr int B_T  = 128 * 80;
    constexpr int STG  = 2 * A_T + 2 * B_T;

    extern __shared__ char smc[];
    uint32_t base = smem_u32(smc);
    int t = threadIdx.x, warp = t >> 5, lane = t & 31;
    int m0 = blockIdx.y * CM, n0 = blockIdx.x * 128;
    int z  = blockIdx.z;
    int wm = warp >> 2, wn = warp & 3;

    const __nv_bfloat16* Ah = Ahi + batchA * z;
    const __nv_bfloat16* Al = Alo + batchA * z;
    const __nv_bfloat16* Bh = Bhi + batchB * z;
    const __nv_bfloat16* Bl = Blo + batchB * z;

    float acc[MT][4][4];
#pragma unroll
    for (int i = 0; i < MT; i++)
#pragma unroll
        for (int j = 0; j < 4; j++)
#pragma unroll
            for (int r = 0; r < 4; r++) acc[i][j][r] = 0.f;

    const int niter = K >> 5;

    auto issue = [&](int it) {
        uint32_t sb = base + (it & 1) * STG;
        int k0 = it << 5;
#pragma unroll
        for (int p = 0; p < CM / 64; p++) {
            int c = t + p * 256;
            int row = c >> 2, j = c & 3;
            const __nv_bfloat16* sh = Ah + (size_t)(m0 + row) * lda + k0 + j * 8;
            const __nv_bfloat16* sl = Al + (size_t)(m0 + row) * lda + k0 + j * 8;
            uint32_t d = sb + (uint32_t)(row * 80 + j * 16);
            CP16(d, sh);
            CP16(d + A_T, sl);
        }
#pragma unroll
        for (int p = 0; p < 2; p++) {
            int c = t + p * 256;
            int row = c >> 2, j = c & 3;
            const __nv_bfloat16* sh = Bh + (size_t)(n0 + row) * ldb + k0 + j * 8;
            const __nv_bfloat16* sl = Bl + (size_t)(n0 + row) * ldb + k0 + j * 8;
            uint32_t d = sb + 2 * A_T + (uint32_t)(row * 80 + j * 16);
            CP16(d, sh);
            CP16(d + B_T, sl);
        }
    };

    issue(0); CP_COMMIT();

    uint32_t a_off = (uint32_t)((wm * (16 * MT) + (lane & 15)) * 80 + (lane >> 4) * 16);
    uint32_t b_off = (uint32_t)((wn * 32 + (lane & 15)) * 80 + (lane >> 4) * 16);

    for (int it = 0; it < niter; ++it) {
        CP_WAIT0();
        __syncthreads();
        if (it + 1 < niter) { issue(it + 1); CP_COMMIT(); }

        uint32_t sb = base + (it & 1) * STG;
        uint32_t sa_h = sb, sa_l = sb + A_T;
        uint32_t sb_h = sb + 2 * A_T, sb_l = sb + 2 * A_T + B_T;

#pragma unroll
        for (int ks = 0; ks < 2; ks++) {
            uint32_t kb = ks * 32;
            uint32_t ah[MT][4], al[MT][4], bh[2][4], bl[2][4];
#pragma unroll
            for (int mt = 0; mt < MT; mt++) {
                uint32_t o = a_off + mt * 16 * 80 + kb;
                LDSM4(ah[mt], sa_h + o);
                LDSM4(al[mt], sa_l + o);
            }
#pragma unroll
            for (int bt = 0; bt < 2; bt++) {
                uint32_t o = b_off + bt * 16 * 80 + kb;
                LDSM4(bh[bt], sb_h + o);
                LDSM4(bl[bt], sb_l + o);
            }
#pragma unroll
            for (int mt = 0; mt < MT; mt++)
#pragma unroll
                for (int nt = 0; nt < 4; nt++)
                    MMA_BF16(acc[mt][nt], ah[mt], bh[nt >> 1][nt & 1], bh[nt >> 1][(nt & 1) + 2]);
#pragma unroll
            for (int mt = 0; mt < MT; mt++)
#pragma unroll
                for (int nt = 0; nt < 4; nt++)
                    MMA_BF16(acc[mt][nt], al[mt], bh[nt >> 1][nt & 1], bh[nt >> 1][(nt & 1) + 2]);
#pragma unroll
            for (int mt = 0; mt < MT; mt++)
#pragma unroll
                for (int nt = 0; nt < 4; nt++)
                    MMA_BF16(acc[mt][nt], ah[mt], bl[nt >> 1][nt & 1], bl[nt >> 1][(nt & 1) + 2]);
        }
    }

    // ---- epilogue ----
    int g = lane >> 2, c2 = lane & 3;
#pragma unroll
    for (int mt = 0; mt < MT; mt++) {
#pragma unroll
        for (int nt = 0; nt < 4; nt++) {
            int row = m0 + wm * (16 * MT) + mt * 16 + g;
            int col = n0 + wn * 32 + nt * 8 + 2 * c2;
            float v[4] = {acc[mt][nt][0], acc[mt][nt][1], acc[mt][nt][2], acc[mt][nt][3]};
            if (mode == 4) {
#pragma unroll
                for (int rr = 0; rr < 2; rr++) {
                    size_t idx = (size_t)((z >> 3) * 512 + row + rr * 8) * 2048
                               + 1024 + (z & 7) * 128 + col;
                    bf16x2_split_store(g_cat_hi, g_cat_lo, idx, v[2 * rr], v[2 * rr + 1]);
                }
                continue;
            }
            if (mode == 3) {
                v[0] *= scale; v[1] *= scale; v[2] *= scale; v[3] *= scale;
            } else if (mode == 0) {
                if (col < 1024) {
                    float sc0 = rsqrtf(bn_var[col] + 1e-5f) * bn_w[col];
                    float sc1 = rsqrtf(bn_var[col + 1] + 1e-5f) * bn_w[col + 1];
                    float of0 = (biasA[col] - bn_mean[col]) * sc0 + bn_b[col];
                    float of1 = (biasA[col + 1] - bn_mean[col + 1]) * sc1 + bn_b[col + 1];
                    v[0] = v[0] * sc0 + of0; v[1] = v[1] * sc1 + of1;
                    v[2] = v[2] * sc0 + of0; v[3] = v[3] * sc1 + of1;
#pragma unroll
                    for (int rr = 0; rr < 2; rr++)
                        bf16x2_split_store(g_qbn_hi, g_qbn_lo,
                                           (size_t)(row + rr * 8) * 1024 + col,
                                           v[2 * rr], v[2 * rr + 1]);
                    continue;
                }
                float b0 = biasB[col - 1024], b1 = biasB[col + 1 - 1024];
                v[0] += b0; v[1] += b1; v[2] += b0; v[3] += b1;
                if (col < 3072) {
                    int cc   = (col < 2048) ? col - 1024 : col - 2048;
                    int h    = cc >> 7, d = cc & 127;
                    __nv_bfloat16* oh = (col < 2048) ? g_qa_hi : g_ka_hi;
                    __nv_bfloat16* ol = (col < 2048) ? g_qa_lo : g_ka_lo;
#pragma unroll
                    for (int rr = 0; rr < 2; rr++) {
                        int token = row + rr * 8;
                        int zz = (token >> 9) * 8 + h;
                        size_t idx = (size_t)zz * (TSEQ * HD)
                                   + (size_t)(token & 511) * HD + d;
                        bf16x2_split_store(oh, ol, idx, v[2 * rr], v[2 * rr + 1]);
                    }
                }
            } else if (mode == 1) {
                if (z == 0) {
                    float b0 = biasA[col] + biasB[col];
                    float b1 = biasA[col + 1] + biasB[col + 1];
                    v[0] += b0; v[1] += b1; v[2] += b0; v[3] += b1;
                }
            }
            float* C; int ld, cc;
            if (col < ncut) { C = C0; ld = ld0; cc = col; }
            else            { C = C1; ld = ld1; cc = col - ncut; }
            C += batchC * z;
            *(float2*)(C + (size_t)row * ld + cc)       = make_float2(v[0], v[1]);
            *(float2*)(C + (size_t)(row + 8) * ld + cc) = make_float2(v[2], v[3]);
        }
    }
}

// ============================================================================
// fused softmax + head-mean + P bf16 split (R12)
// ============================================================================
__global__ void __launch_bounds__(512) attn_softmax_mean(float* __restrict__ attn_w)
{
    int bq = blockIdx.x;
    int b  = bq >> 9, qi = bq & 511;
    int t  = threadIdx.x;
    int g  = t >> 6;
    int u  = t & 63;
    int w  = t >> 5;

    __shared__ float sp[8][512];
    __shared__ float red[32];

    int z = b * 8 + g;
    const float* arow = g_att + ((size_t)z * TSEQ + qi) * TSEQ;

    float v[8];
    float mx = -INFINITY;
#pragma unroll
    for (int i = 0; i < 8; i++) {
        v[i] = arow[u + i * 64];
        mx = fmaxf(mx, v[i]);
    }
#pragma unroll
    for (int off = 16; off; off >>= 1)
        mx = fmaxf(mx, __shfl_xor_sync(0xffffffffu, mx, off));
    if ((t & 31) == 0) red[w] = mx;
    __syncthreads();
    float hm = fmaxf(red[2 * g], red[2 * g + 1]);

    float e[8], s = 0.f;
#pragma unroll
    for (int i = 0; i < 8; i++) { e[i] = expf(v[i] - hm); s += e[i]; }
#pragma unroll
    for (int off = 16; off; off >>= 1)
        s += __shfl_xor_sync(0xffffffffu, s, off);
    if ((t & 31) == 0) red[16 + w] = s;
    __syncthreads();
    float inv = 1.f / (red[16 + 2 * g] + red[16 + 2 * g + 1]);

    size_t pbase = ((size_t)z * TSEQ + qi) * TSEQ;
#pragma unroll
    for (int i = 0; i < 8; i++) {
        float p = e[i] * inv;
        int k = u + i * 64;
        sp[g][k] = p;
        __nv_bfloat16 h = __float2bfloat16(p);
        g_p_hi[pbase + k] = h;
        g_p_lo[pbase + k] = __float2bfloat16(p - __bfloat162float(h));
    }
    __syncthreads();

    float m8 = 0.f;
#pragma unroll
    for (int h = 0; h < 8; h++) m8 += sp[h][t];
    attn_w[(size_t)bq * TSEQ + t] = m8 * 0.125f;
}

// ============================================================================
// V transpose
// ============================================================================
__global__ void __launch_bounds__(256) v_transpose()
{
    int z = blockIdx.z;
    int b = z >> 3, h = z & 7;
    int k0 = blockIdx.x * 32, e0 = blockIdx.y * 32;
    __shared__ float tile[32][33];
    int tx = threadIdx.x & 31, ty = threadIdx.x >> 5;

#pragma unroll
    for (int s = 0; s < 4; s++) {
        int k = k0 + ty + s * 8;
        tile[ty + s * 8][tx] =
            g_qkv[(size_t)(b * TSEQ + k) * (3 * DMODEL) + 2 * DMODEL + h * HD + e0 + tx];
    }
    __syncthreads();
#pragma unroll
    for (int s = 0; s < 4; s++) {
        int e = e0 + ty + s * 8;
        float v = tile[tx][ty + s * 8];
        size_t idx = (size_t)z * (HD * TSEQ) + (size_t)e * TSEQ + k0 + tx;
        __nv_bfloat16 hh = __float2bfloat16(v);
        g_vt_hi[idx] = hh;
        g_vt_lo[idx] = __float2bfloat16(v - __bfloat162float(hh));
    }
}

// ============================================================================
// PEER routing (measured-best R9/R12 version)
// ============================================================================
__global__ void __launch_bounds__(128) peer_route(const float* __restrict__ expert_w)
{
    int row   = blockIdx.x;
    int token = row >> 3;
    int head  = row & 7;
    int tid   = threadIdx.x;

    __shared__ float q[128];
    __shared__ float sh1[128], sh2[128];
    __shared__ float v1[16], v2[16];
    __shared__ int   i1[16], i2[16];
    __shared__ float cv[50];
    __shared__ int   ci[50];
    __shared__ int   sel[16];
    __shared__ float simv[16];
    __shared__ float rw[16];
    __shared__ float ews[16][128];

    size_t qidx = (size_t)token * HK + head * 128 + tid;
    q[tid] = __bfloat162float(g_qbn_hi[qidx]) + __bfloat162float(g_qbn_lo[qidx]);
    float s1v = g_s[(size_t)row * 256 + tid];
    float s2v = g_s[(size_t)row * 256 + 128 + tid];
    sh1[tid] = s1v; sh2[tid] = s2v;
    __syncthreads();

    int r1 = 0, r2 = 0;
#pragma unroll 8
    for (int j = 0; j < 128; j++) {
        float w1 = sh1[j]; r1 += (w1 > s1v) || (w1 == s1v && j < tid);
        float w2 = sh2[j]; r2 += (w2 > s2v) || (w2 == s2v && j < tid);
    }
    if (r1 < 16) { v1[r1] = s1v; i1[r1] = tid; }
    if (r2 < 16) { v2[r2] = s2v; i2[r2] = tid; }
    __syncthreads();

    if (tid < 50) {
        int a = CAND_A[tid], b = CAND_B[tid];
        cv[tid] = v1[a] + v2[b];
        ci[tid] = i1[a] * NSUB + i2[b];
    }
    __syncthreads();
    if (tid < 50) {
        float v = cv[tid];
        int r = 0;
#pragma unroll 10
        for (int j = 0; j < 50; j++) {
            float w = cv[j];
            r += (w > v) || (w == v && j < tid);
        }
        if (r < 16) sel[r] = ci[tid];
    }
    __syncthreads();

#pragma unroll
    for (int k = 0; k < 16; k++)
        ews[k][tid] = expert_w[(size_t)sel[k] * DKEY + tid];
    __syncthreads();

    int k8 = tid >> 3, l8 = tid & 7;
    float part = 0.f;
#pragma unroll
    for (int i = 0; i < 16; i++) {
        int d = l8 * 16 + i;
        part += q[d] * ews[k8][d];
    }
    part += __shfl_down_sync(0xffffffffu, part, 4);
    part += __shfl_down_sync(0xffffffffu, part, 2);
    part += __shfl_down_sync(0xffffffffu, part, 1);
    if (l8 == 0) simv[k8] = part;
    __syncthreads();

    if (tid == 0) {
        float m = -INFINITY;
#pragma unroll
        for (int k = 0; k < 16; k++) m = fmaxf(m, simv[k]);
        float e[16]; float s = 0.f;
#pragma unroll
        for (int k = 0; k < 16; k++) { e[k] = expf(simv[k] - m); s += e[k]; }
        float inv = 1.f / s;
#pragma unroll
        for (int k = 0; k < 16; k++) rw[k] = e[k] * inv;
    }
    __syncthreads();

    float o = 0.f;
#pragma unroll
    for (int k = 0; k < 16; k++) o += rw[k] * ews[k][tid];
    size_t idx = (size_t)token * 2048 + head * 128 + tid;
    __nv_bfloat16 h = __float2bfloat16(o);
    g_cat_hi[idx] = h;
    g_cat_lo[idx] = __float2bfloat16(o - __bfloat162float(h));
}

// y = rmsnorm(x + g_sum[0] + g_sum[1]) * rms_w
__global__ void __launch_bounds__(256) final_rms(
    const float* __restrict__ x, const float* __restrict__ rms_w,
    float* __restrict__ y)
{
    int token = blockIdx.x;
    int t = threadIdx.x;
    size_t base = (size_t)token * DMODEL;
    const size_t half = (size_t)NTOK * DMODEL;
    float v[4];
    float ss = 0.f;
#pragma unroll
    for (int u = 0; u < 4; u++) {
        int c = t + u * 256;
        float s = x[base + c] + g_sum[base + c] + g_sum[half + base + c];
        v[u] = s;
        ss += s * s;
    }
#pragma unroll
    for (int off = 16; off; off >>= 1)
        ss += __shfl_xor_sync(0xffffffffu, ss, off);
    __shared__ float red[8];
    __shared__ float stot;
    if ((t & 31) == 0) red[t >> 5] = ss;
    __syncthreads();
    if (t == 0) {
        float s = 0.f;
#pragma unroll
        for (int i = 0; i < 8; i++) s += red[i];
        stot = rsqrtf(s * (1.f / DMODEL) + 1e-6f);
    }
    __syncthreads();
    float inv = stot;
#pragma unroll
    for (int u = 0; u < 4; u++) {
        int c = t + u * 256;
        y[base + c] = v[u] * inv * rms_w[c];
    }
}

// ============================================================================
extern "C" void kernel_launch(void* const* d_in, const int* in_sizes, int n_in,
                              void* d_out, int out_size)
{
    const float* x         = (const float*)d_in[0];
    const float* wq        = (const float*)d_in[1];
    const float* bq        = (const float*)d_in[2];
    const float* bn_w      = (const float*)d_in[3];
    const float* bn_b      = (const float*)d_in[4];
    const float* bn_mean   = (const float*)d_in[5];
    const float* bn_var    = (const float*)d_in[6];
    const float* sub_keys  = (const float*)d_in[7];
    const float* expert_w  = (const float*)d_in[8];
    const float* wo        = (const float*)d_in[9];
    const float* bo        = (const float*)d_in[10];
    const float* in_proj_w = (const float*)d_in[11];
    const float* in_proj_b = (const float*)d_in[12];
    const float* attn_ow   = (const float*)d_in[13];
    const float* attn_ob   = (const float*)d_in[14];
    const float* rms_w     = (const float*)d_in[15];

    float* y      = (float*)d_out;
    float* attn_w = (float*)d_out + (size_t)NTOK * DMODEL;

    void *p_qkv, *p_sum, *p_s, *p_att;
    cudaGetSymbolAddress(&p_qkv, g_qkv);
    cudaGetSymbolAddress(&p_sum, g_sum);
    cudaGetSymbolAddress(&p_s, g_s);
    cudaGetSymbolAddress(&p_att, g_att);

    void *xh, *xl, *w1h, *w1l, *w2h, *w2l, *ch, *cl, *qbh, *qbl, *bdh, *bdl;
    void *qah, *qal, *kah, *kal, *ph, *pl, *vth, *vtl;
    cudaGetSymbolAddress(&xh,  g_x_hi);  cudaGetSymbolAddress(&xl,  g_x_lo);
    cudaGetSymbolAddress(&w1h, g_w1_hi); cudaGetSymbolAddress(&w1l, g_w1_lo);
    cudaGetSymbolAddress(&w2h, g_w2_hi); cudaGetSymbolAddress(&w2l, g_w2_lo);
    cudaGetSymbolAddress(&ch,  g_cat_hi); cudaGetSymbolAddress(&cl, g_cat_lo);
    cudaGetSymbolAddress(&qbh, g_qbn_hi); cudaGetSymbolAddress(&qbl, g_qbn_lo);
    cudaGetSymbolAddress(&bdh, g_bd_hi); cudaGetSymbolAddress(&bdl, g_bd_lo);
    cudaGetSymbolAddress(&qah, g_qa_hi); cudaGetSymbolAddress(&qal, g_qa_lo);
    cudaGetSymbolAddress(&kah, g_ka_hi); cudaGetSymbolAddress(&kal, g_ka_lo);
    cudaGetSymbolAddress(&ph,  g_p_hi);  cudaGetSymbolAddress(&pl,  g_p_lo);
    cudaGetSymbolAddress(&vth, g_vt_hi); cudaGetSymbolAddress(&vtl, g_vt_lo);

    constexpr int SMEM4 = 2 * (2 * 128 * 80 + 2 * 128 * 80);  // 81920
    constexpr int SMEM2 = 2 * (2 * 64 * 80 + 2 * 128 * 80);   // 61440
    cudaFuncSetAttribute(gemm_mma<4>, cudaFuncAttributeMaxDynamicSharedMemorySize, SMEM4);
    cudaFuncSetAttribute(gemm_mma<2>, cudaFuncAttributeMaxDynamicSharedMemorySize, SMEM2);

    const float scale = 0.08838834764831845f;   // 1/sqrt(128)

    // fork/join events (created per call; harness calls kernel_launch twice)
    cudaEvent_t ev_fork, ev_join;
    cudaEventCreateWithFlags(&ev_fork, cudaEventDisableTiming);
    cudaEventCreateWithFlags(&ev_join, cudaEventDisableTiming);
    cudaStream_t sB = cudaStreamPerThread;

    // ---- legacy stream: split + gemm1 ----
    split_all<<<(int)((X4 + W14 + W24 + BD4) / 256), 256>>>(
        x, wq, in_proj_w, wo, attn_ow, sub_keys);

    gemm_mma<4><<<dim3(4096 / 128, NTOK / 128), 256, SMEM4>>>(
        (const __nv_bfloat16*)xh, (const __nv_bfloat16*)xl,
        (const __nv_bfloat16*)w1h, (const __nv_bfloat16*)w1l,
        DMODEL, DMODEL, 0, 0,
        bq, in_proj_b, bn_mean, bn_var, bn_w, bn_b,
        0, 1.f,
        (float*)p_qkv, 3 * DMODEL, (float*)p_qkv, 3 * DMODEL, 1024, 0, DMODEL);

    cudaEventRecord(ev_fork, 0);
    cudaStreamWaitEvent(sB, ev_fork, 0);

    // ---- stream B: PEER chain (ALU-heavy) ----
    gemm_mma<4><<<dim3(2, 64), 256, SMEM4, sB>>>(
        (const __nv_bfloat16*)qbh, (const __nv_bfloat16*)qbl,
        (const __nv_bfloat16*)bdh, (const __nv_bfloat16*)bdl,
        128, 128, 0, 0,
        nullptr, nullptr, nullptr, nullptr, nullptr, nullptr,
        2, 1.f,
        (float*)p_s, 256, (float*)p_s, 256, 1 << 30, 0, 128);

    peer_route<<<NTOK * NHEADS, 128, 0, sB>>>(expert_w);
    cudaEventRecord(ev_join, sB);

    // ---- legacy stream: attention chain (tensor/mem-heavy) ----
    gemm_mma<4><<<dim3(4, 4, NZ), 256, SMEM4>>>(
        (const __nv_bfloat16*)qah, (const __nv_bfloat16*)qal,
        (const __nv_bfloat16*)kah, (const __nv_bfloat16*)kal,
        HD, HD, (size_t)TSEQ * HD, (size_t)TSEQ * HD,
        nullptr, nullptr, nullptr, nullptr, nullptr, nullptr,
        3, scale,
        (float*)p_att, TSEQ, (float*)p_att, TSEQ, 1 << 30,
        (size_t)TSEQ * TSEQ, HD);

    attn_softmax_mean<<<NTOK, 512>>>(attn_w);

    v_transpose<<<dim3(TSEQ / 32, HD / 32, NZ), 256>>>();

    gemm_mma<2><<<dim3(1, 8, NZ), 256, SMEM2>>>(
        (const __nv_bfloat16*)ph, (const __nv_bfloat16*)pl,
        (const __nv_bfloat16*)vth, (const __nv_bfloat16*)vtl,
        TSEQ, TSEQ, (size_t)TSEQ * TSEQ, (size_t)HD * TSEQ,
        nullptr, nullptr, nullptr, nullptr, nullptr, nullptr,
        4, 1.f,
        nullptr, 0, nullptr, 0, 1 << 30, 0, TSEQ);

    // ---- join: output projection (split-K x2) + rmsnorm on legacy ----
    cudaStreamWaitEvent(0, ev_join, 0);

    gemm_mma<2><<<dim3(DMODEL / 128, NTOK / 64, 2), 256, SMEM2>>>(
        (const __nv_bfloat16*)ch, (const __nv_bfloat16*)cl,
        (const __nv_bfloat16*)w2h, (const __nv_bfloat16*)w2l,
        2048, 2048, 1024, 1024,
        bo, attn_ob, nullptr, nullptr, nullptr, nullptr,
        1, 1.f,
        (float*)p_sum, DMODEL, (float*)p_sum, DMODEL, 1 << 30,
        (size_t)NTOK * DMODEL, 1024);

    final_rms<<<NTOK, 256>>>(x, rms_w, y);

    cudaEventDestroy(ev_fork);
    cudaEventDestroy(ev_join);

    (void)in_sizes; (void)n_in; (void)out_size;
}

// round 14
// speedup vs baseline: 1.1020x; 1.0102x over previous
#include <cuda_runtime.h>
#include <cuda_bf16.h>
#include <math.h>
#include <stdint.h>

// ---------------- problem constants ----------------
#define BATCH   2
#define TSEQ    512
#define NTOK    1024
#define DMODEL  1024
#define NHEADS  8
#define DKEY    128
#define HK      1024
#define NSUB    128
#define TOPK    16
#define HD      128
#define NZ      16        // BATCH*NHEADS

// ---------------- scratch ----------------
__device__ __align__(128) float g_qkv[NTOK * 3 * DMODEL];
__device__ __align__(128) float g_att[NZ * TSEQ * TSEQ];   // raw scores
__device__ __align__(128) float g_sum[2 * NTOK * DMODEL];  // split-K partials
__device__ __align__(128) float g_s[NTOK * NHEADS * 256];

__device__ __align__(128) __nv_bfloat16 g_x_hi[NTOK * DMODEL],  g_x_lo[NTOK * DMODEL];
__device__ __align__(128) __nv_bfloat16 g_w1_hi[4096 * DMODEL], g_w1_lo[4096 * DMODEL];
__device__ __align__(128) __nv_bfloat16 g_w2_hi[DMODEL * 2048], g_w2_lo[DMODEL * 2048];
__device__ __align__(128) __nv_bfloat16 g_cat_hi[NTOK * 2048],  g_cat_lo[NTOK * 2048];
__device__ __align__(128) __nv_bfloat16 g_qbn_hi[NTOK * HK],    g_qbn_lo[NTOK * HK];
__device__ __align__(128) __nv_bfloat16 g_bd_hi[256 * 128],     g_bd_lo[256 * 128];
__device__ __align__(128) __nv_bfloat16 g_qa_hi[NZ * TSEQ * HD], g_qa_lo[NZ * TSEQ * HD];
__device__ __align__(128) __nv_bfloat16 g_ka_hi[NZ * TSEQ * HD], g_ka_lo[NZ * TSEQ * HD];
__device__ __align__(128) __nv_bfloat16 g_p_hi[NZ * TSEQ * TSEQ], g_p_lo[NZ * TSEQ * TSEQ];
__device__ __align__(128) __nv_bfloat16 g_vt_hi[NZ * HD * TSEQ],  g_vt_lo[NZ * HD * TSEQ];

// 50 candidates (a,b) with (a+1)(b+1) <= 16 over rank-sorted v1,v2
__device__ const int CAND_A[50] = {0,0,0,0,0,0,0,0,0,0,0,0,0,0,0,0,
                                   1,1,1,1,1,1,1,1, 2,2,2,2,2, 3,3,3,3,
                                   4,4,4, 5,5, 6,6, 7,7, 8,9,10,11,12,13,14,15};
__device__ const int CAND_B[50] = {0,1,2,3,4,5,6,7,8,9,10,11,12,13,14,15,
                                   0,1,2,3,4,5,6,7, 0,1,2,3,4, 0,1,2,3,
                                   0,1,2, 0,1, 0,1, 0,1, 0,0,0,0,0,0,0,0};

// ---------------- helpers ----------------
__device__ __forceinline__ uint32_t smem_u32(const void* p) {
    uint32_t a;
    asm("{ .reg .u64 t; cvta.to.shared.u64 t, %1; cvt.u32.u64 %0, t; }"
        : "=r"(a) : "l"(p));
    return a;
}
#define LDSM4(r, addr) \
    asm volatile("ldmatrix.sync.aligned.m8n8.x4.shared.b16 {%0,%1,%2,%3}, [%4];" \
        : "=r"((r)[0]), "=r"((r)[1]), "=r"((r)[2]), "=r"((r)[3]) : "r"(addr))
#define MMA_BF16(d, a, b0, b1) \
    asm volatile("mma.sync.aligned.m16n8k16.row.col.f32.bf16.bf16.f32 " \
        "{%0,%1,%2,%3}, {%4,%5,%6,%7}, {%8,%9}, {%0,%1,%2,%3};" \
        : "+f"((d)[0]), "+f"((d)[1]), "+f"((d)[2]), "+f"((d)[3]) \
        : "r"((a)[0]), "r"((a)[1]), "r"((a)[2]), "r"((a)[3]), "r"(b0), "r"(b1))
#define CP16(dst, src) \
    asm volatile("cp.async.cg.shared.global [%0], [%1], 16;" :: "r"(dst), "l"(src))
#define CP_COMMIT() asm volatile("cp.async.commit_group;" ::: "memory")
#define CP_WAIT0()  asm volatile("cp.async.wait_group 0;" ::: "memory")

__device__ __forceinline__ void bf16x2_split_store(__nv_bfloat16* hi, __nv_bfloat16* lo,
                                                   size_t idx, float a, float b) {
    __nv_bfloat16 h0 = __float2bfloat16(a);
    __nv_bfloat16 h1 = __float2bfloat16(b);
    *(__nv_bfloat162*)(hi + idx) = __nv_bfloat162(h0, h1);
    *(__nv_bfloat162*)(lo + idx) = __nv_bfloat162(
        __float2bfloat16(a - __bfloat162float(h0)),
        __float2bfloat16(b - __bfloat162float(h1)));
}

// monotone uint mapping of float (order-preserving)
__device__ __forceinline__ uint32_t fmono(float f) {
    uint32_t b = __float_as_uint(f);
    return b ^ (uint32_t)(((int32_t)b >> 31) | 0x80000000);
}

// ============================================================================
// combined split kernel
// ============================================================================
__device__ __forceinline__ void split_store4(float4 v, __nv_bfloat16* hi,
                                             __nv_bfloat16* lo, size_t i4) {
    float vv[4] = {v.x, v.y, v.z, v.w};
    __nv_bfloat16 h[4], l[4];
#pragma unroll
    for (int k = 0; k < 4; k++) {
        h[k] = __float2bfloat16(vv[k]);
        l[k] = __float2bfloat16(vv[k] - __bfloat162float(h[k]));
    }
    ((__nv_bfloat162*)hi)[2 * i4]     = __nv_bfloat162(h[0], h[1]);
    ((__nv_bfloat162*)hi)[2 * i4 + 1] = __nv_bfloat162(h[2], h[3]);
    ((__nv_bfloat162*)lo)[2 * i4]     = __nv_bfloat162(l[0], l[1]);
    ((__nv_bfloat162*)lo)[2 * i4 + 1] = __nv_bfloat162(l[2], l[3]);
}

#define X4   ((size_t)NTOK * DMODEL / 4)
#define W14  ((size_t)4096 * DMODEL / 4)
#define W24  ((size_t)DMODEL * 2048 / 4)
#define BD4  ((size_t)256 * 128 / 4)

__global__ void __launch_bounds__(256) split_all(
    const float* __restrict__ x,  const float* __restrict__ wq,
    const float* __restrict__ ipw, const float* __restrict__ wo,
    const float* __restrict__ aow, const float* __restrict__ sub_keys)
{
    size_t i = (size_t)blockIdx.x * 256 + threadIdx.x;
    if (i < X4) {
        split_store4(((const float4*)x)[i], g_x_hi, g_x_lo, i);
    } else if (i < X4 + W14) {
        size_t j = i - X4;
        const size_t cut = (size_t)1024 * 1024 / 4;
        float4 v = (j < cut) ? ((const float4*)wq)[j] : ((const float4*)ipw)[j - cut];
        split_store4(v, g_w1_hi, g_w1_lo, j);
    } else if (i < X4 + W14 + W24) {
        size_t j = i - X4 - W14;
        int row = (int)(j >> 9);
        int c4  = (int)(j & 511);
        float4 v = (c4 < 256) ? ((const float4*)wo)[row * 256 + c4]
                              : ((const float4*)aow)[row * 256 + c4 - 256];
        split_store4(v, g_w2_hi, g_w2_lo, j);
    } else {
        size_t j = i - X4 - W14 - W24;
        int row = (int)(j >> 5);
        int c4  = (int)(j & 31);
        float4 v = make_float4(0.f, 0.f, 0.f, 0.f);
        if (row < 128 && c4 < 16)
            v = ((const float4*)sub_keys)[row * 16 + c4];
        else if (row >= 128 && c4 >= 16)
            v = ((const float4*)(sub_keys + 128 * 64))[(row - 128) * 16 + (c4 - 16)];
        split_store4(v, g_bd_hi, g_bd_lo, j);
    }
}

// ============================================================================
// bf16-split "3M" GEMM
// ============================================================================
template<int MT>
__global__ void __launch_bounds__(256, 2) gemm_mma(
    const __nv_bfloat16* __restrict__ Ahi, const __nv_bfloat16* __restrict__ Alo,
    const __nv_bfloat16* __restrict__ Bhi, const __nv_bfloat16* __restrict__ Blo,
    int lda, int ldb, size_t batchA, size_t batchB,
    const float* __restrict__ biasA, const float* __restrict__ biasB,
    const float* __restrict__ bn_mean, const float* __restrict__ bn_var,
    const float* __restrict__ bn_w, const float* __restrict__ bn_b,
    int mode, float scale,
    float* __restrict__ C0, int ld0, float* __restrict__ C1, int ld1, int ncut,
    size_t batchC, int K)
{
    constexpr int CM   = 32 * MT;
    constexpr int A_T  = CM * 80;
    constexpr int B_T  = 128 * 80;
    constexpr int STG  = 2 * A_T + 2 * B_T;

    extern __shared__ char smc[];
    uint32_t base = smem_u32(smc);
    int t = threadIdx.x, warp = t >> 5, lane = t & 31;
    int m0 = blockIdx.y * CM, n0 = blockIdx.x * 128;
    int z  = blockIdx.z;
    int wm = warp >> 2, wn = warp & 3;

    const __nv_bfloat16* Ah = Ahi + batchA * z;
    const __nv_bfloat16* Al = Alo + batchA * z;
    const __nv_bfloat16* Bh = Bhi + batchB * z;
    const __nv_bfloat16* Bl = Blo + batchB * z;

    float acc[MT][4][4];
#pragma unroll
    for (int i = 0; i < MT; i++)
#pragma unroll
        for (int j = 0; j < 4; j++)
#pragma unroll
            for (int r = 0; r < 4; r++) acc[i][j][r] = 0.f;

    const int niter = K >> 5;

    auto issue = [&](int it) {
        uint32_t sb = base + (it & 1) * STG;
        int k0 = it << 5;
#pragma unroll
        for (int p = 0; p < CM / 64; p++) {
            int c = t + p * 256;
            int row = c >> 2, j = c & 3;
            const __nv_bfloat16* sh = Ah + (size_t)(m0 + row) * lda + k0 + j * 8;
            const __nv_bfloat16* sl = Al + (size_t)(m0 + row) * lda + k0 + j * 8;
            uint32_t d = sb + (uint32_t)(row * 80 + j * 16);
            CP16(d, sh);
            CP16(d + A_T, sl);
        }
#pragma unroll
        for (int p = 0; p < 2; p++) {
            int c = t + p * 256;
            int row = c >> 2, j = c & 3;
            const __nv_bfloat16* sh = Bh + (size_t)(n0 + row) * ldb + k0 + j * 8;
            const __nv_bfloat16* sl = Bl + (size_t)(n0 + row) * ldb + k0 + j * 8;
            uint32_t d = sb + 2 * A_T + (uint32_t)(row * 80 + j * 16);
            CP16(d, sh);
            CP16(d + B_T, sl);
        }
    };

    issue(0); CP_COMMIT();

    uint32_t a_off = (uint32_t)((wm * (16 * MT) + (lane & 15)) * 80 + (lane >> 4) * 16);
    uint32_t b_off = (uint32_t)((wn * 32 + (lane & 15)) * 80 + (lane >> 4) * 16);

    for (int it = 0; it < niter; ++it) {
        CP_WAIT0();
        __syncthreads();
        if (it + 1 < niter) { issue(it + 1); CP_COMMIT(); }

        uint32_t sb = base + (it & 1) * STG;
        uint32_t sa_h = sb, sa_l = sb + A_T;
        uint32_t sb_h = sb + 2 * A_T, sb_l = sb + 2 * A_T + B_T;

#pragma unroll
        for (int ks = 0; ks < 2; ks++) {
            uint32_t kb = ks * 32;
            uint32_t ah[MT][4], al[MT][4], bh[2][4], bl[2][4];
#pragma unroll
            for (int mt = 0; mt < MT; mt++) {
                uint32_t o = a_off + mt * 16 * 80 + kb;
                LDSM4(ah[mt], sa_h + o);
                LDSM4(al[mt], sa_l + o);
            }
#pragma unroll
            for (int bt = 0; bt < 2; bt++) {
                uint32_t o = b_off + bt * 16 * 80 + kb;
                LDSM4(bh[bt], sb_h + o);
                LDSM4(bl[bt], sb_l + o);
            }
#pragma unroll
            for (int mt = 0; mt < MT; mt++)
#pragma unroll
                for (int nt = 0; nt < 4; nt++)
                    MMA_BF16(acc[mt][nt], ah[mt], bh[nt >> 1][nt & 1], bh[nt >> 1][(nt & 1) + 2]);
#pragma unroll
            for (int mt = 0; mt < MT; mt++)
#pragma unroll
                for (int nt = 0; nt < 4; nt++)
                    MMA_BF16(acc[mt][nt], al[mt], bh[nt >> 1][nt & 1], bh[nt >> 1][(nt & 1) + 2]);
#pragma unroll
            for (int mt = 0; mt < MT; mt++)
#pragma unroll
                for (int nt = 0; nt < 4; nt++)
                    MMA_BF16(acc[mt][nt], ah[mt], bl[nt >> 1][nt & 1], bl[nt >> 1][(nt & 1) + 2]);
        }
    }

    // ---- epilogue ----
    int g = lane >> 2, c2 = lane & 3;
#pragma unroll
    for (int mt = 0; mt < MT; mt++) {
#pragma unroll
        for (int nt = 0; nt < 4; nt++) {
            int row = m0 + wm * (16 * MT) + mt * 16 + g;
            int col = n0 + wn * 32 + nt * 8 + 2 * c2;
            float v[4] = {acc[mt][nt][0], acc[mt][nt][1], acc[mt][nt][2], acc[mt][nt][3]};
            if (mode == 4) {
#pragma unroll
                for (int rr = 0; rr < 2; rr++) {
                    size_t idx = (size_t)((z >> 3) * 512 + row + rr * 8) * 2048
                               + 1024 + (z & 7) * 128 + col;
                    bf16x2_split_store(g_cat_hi, g_cat_lo, idx, v[2 * rr], v[2 * rr + 1]);
                }
                continue;
            }
            if (mode == 3) {
                v[0] *= scale; v[1] *= scale; v[2] *= scale; v[3] *= scale;
            } else if (mode == 0) {
                if (col < 1024) {
                    float sc0 = rsqrtf(bn_var[col] + 1e-5f) * bn_w[col];
                    float sc1 = rsqrtf(bn_var[col + 1] + 1e-5f) * bn_w[col + 1];
                    float of0 = (biasA[col] - bn_mean[col]) * sc0 + bn_b[col];
                    float of1 = (biasA[col + 1] - bn_mean[col + 1]) * sc1 + bn_b[col + 1];
                    v[0] = v[0] * sc0 + of0; v[1] = v[1] * sc1 + of1;
                    v[2] = v[2] * sc0 + of0; v[3] = v[3] * sc1 + of1;
#pragma unroll
                    for (int rr = 0; rr < 2; rr++)
                        bf16x2_split_store(g_qbn_hi, g_qbn_lo,
                                           (size_t)(row + rr * 8) * 1024 + col,
                                           v[2 * rr], v[2 * rr + 1]);
                    continue;
                }
                float b0 = biasB[col - 1024], b1 = biasB[col + 1 - 1024];
                v[0] += b0; v[1] += b1; v[2] += b0; v[3] += b1;
                if (col < 3072) {
                    int cc   = (col < 2048) ? col - 1024 : col - 2048;
                    int h    = cc >> 7, d = cc & 127;
                    __nv_bfloat16* oh = (col < 2048) ? g_qa_hi : g_ka_hi;
                    __nv_bfloat16* ol = (col < 2048) ? g_qa_lo : g_ka_lo;
#pragma unroll
                    for (int rr = 0; rr < 2; rr++) {
                        int token = row + rr * 8;
                        int zz = (token >> 9) * 8 + h;
                        size_t idx = (size_t)zz * (TSEQ * HD)
                                   + (size_t)(token & 511) * HD + d;
                        bf16x2_split_store(oh, ol, idx, v[2 * rr], v[2 * rr + 1]);
                    }
                }
            } else if (mode == 1) {
                if (z == 0) {
                    float b0 = biasA[col] + biasB[col];
                    float b1 = biasA[col + 1] + biasB[col + 1];
                    v[0] += b0; v[1] += b1; v[2] += b0; v[3] += b1;
                }
            }
            float* C; int ld, cc;
            if (col < ncut) { C = C0; ld = ld0; cc = col; }
            else            { C = C1; ld = ld1; cc = col - ncut; }
            C += batchC * z;
            *(float2*)(C + (size_t)row * ld + cc)       = make_float2(v[0], v[1]);
            *(float2*)(C + (size_t)(row + 8) * ld + cc) = make_float2(v[2], v[3]);
        }
    }
}

// ============================================================================
// fused softmax + head-mean + P bf16 split
// ============================================================================
__global__ void __launch_bounds__(512) attn_softmax_mean(float* __restrict__ attn_w)
{
    int bq = blockIdx.x;
    int b  = bq >> 9, qi = bq & 511;
    int t  = threadIdx.x;
    int g  = t >> 6;
    int u  = t & 63;
    int w  = t >> 5;

    __shared__ float sp[8][512];
    __shared__ float red[32];

    int z = b * 8 + g;
    const float* arow = g_att + ((size_t)z * TSEQ + qi) * TSEQ;

    float v[8];
    float mx = -INFINITY;
#pragma unroll
    for (int i = 0; i < 8; i++) {
        v[i] = arow[u + i * 64];
        mx = fmaxf(mx, v[i]);
    }
#pragma unroll
    for (int off = 16; off; off >>= 1)
        mx = fmaxf(mx, __shfl_xor_sync(0xffffffffu, mx, off));
    if ((t & 31) == 0) red[w] = mx;
    __syncthreads();
    float hm = fmaxf(red[2 * g], red[2 * g + 1]);

    float e[8], s = 0.f;
#pragma unroll
    for (int i = 0; i < 8; i++) { e[i] = expf(v[i] - hm); s += e[i]; }
#pragma unroll
    for (int off = 16; off; off >>= 1)
        s += __shfl_xor_sync(0xffffffffu, s, off);
    if ((t & 31) == 0) red[16 + w] = s;
    __syncthreads();
    float inv = 1.f / (red[16 + 2 * g] + red[16 + 2 * g + 1]);

    size_t pbase = ((size_t)z * TSEQ + qi) * TSEQ;
#pragma unroll
    for (int i = 0; i < 8; i++) {
        float p = e[i] * inv;
        int k = u + i * 64;
        sp[g][k] = p;
        __nv_bfloat16 h = __float2bfloat16(p);
        g_p_hi[pbase + k] = h;
        g_p_lo[pbase + k] = __float2bfloat16(p - __bfloat162float(h));
    }
    __syncthreads();

    float m8 = 0.f;
#pragma unroll
    for (int h = 0; h < 8; h++) m8 += sp[h][t];
    attn_w[(size_t)bq * TSEQ + t] = m8 * 0.125f;
}

// ============================================================================
// V transpose
// ============================================================================
__global__ void __launch_bounds__(256) v_transpose()
{
    int z = blockIdx.z;
    int b = z >> 3, h = z & 7;
    int k0 = blockIdx.x * 32, e0 = blockIdx.y * 32;
    __shared__ float tile[32][33];
    int tx = threadIdx.x & 31, ty = threadIdx.x >> 5;

#pragma unroll
    for (int s = 0; s < 4; s++) {
        int k = k0 + ty + s * 8;
        tile[ty + s * 8][tx] =
            g_qkv[(size_t)(b * TSEQ + k) * (3 * DMODEL) + 2 * DMODEL + h * HD + e0 + tx];
    }
    __syncthreads();
#pragma unroll
    for (int s = 0; s < 4; s++) {
        int e = e0 + ty + s * 8;
        float v = tile[tx][ty + s * 8];
        size_t idx = (size_t)z * (HD * TSEQ) + (size_t)e * TSEQ + k0 + tx;
        __nv_bfloat16 hh = __float2bfloat16(v);
        g_vt_hi[idx] = hh;
        g_vt_lo[idx] = __float2bfloat16(v - __bfloat162float(hh));
    }
}

// ============================================================================
// PEER routing: 64-bit monotone-key rank loops (1 compare per element)
// ============================================================================
__global__ void __launch_bounds__(128) peer_route(const float* __restrict__ expert_w)
{
    int row   = blockIdx.x;
    int token = row >> 3;
    int head  = row & 7;
    int tid   = threadIdx.x;

    __shared__ float q[128];
    __shared__ unsigned long long k1s[128], k2s[128];
    __shared__ float v1[16], v2[16];
    __shared__ int   i1[16], i2[16];
    __shared__ float cv[50];
    __shared__ int   ci[50];
    __shared__ int   sel[16];
    __shared__ float simv[16];
    __shared__ float rw[16];
    __shared__ float ews[16][128];

    size_t qidx = (size_t)token * HK + head * 128 + tid;
    q[tid] = __bfloat162float(g_qbn_hi[qidx]) + __bfloat162float(g_qbn_lo[qidx]);
    float s1v = g_s[(size_t)row * 256 + tid];
    float s2v = g_s[(size_t)row * 256 + 128 + tid];
    // composite key: (monotone(value) << 7) | (127 - idx)
    // key_j > key_me  <=>  v_j > v_me, or v_j == v_me && j < me
    unsigned long long myk1 = ((unsigned long long)fmono(s1v) << 7) | (unsigned long long)(127 - tid);
    unsigned long long myk2 = ((unsigned long long)fmono(s2v) << 7) | (unsigned long long)(127 - tid);
    k1s[tid] = myk1;
    k2s[tid] = myk2;
    __syncthreads();

    int r1 = 0, r2 = 0;
#pragma unroll 16
    for (int j = 0; j < 128; j++) {
        r1 += (k1s[j] > myk1);
        r2 += (k2s[j] > myk2);
    }
    if (r1 < 16) { v1[r1] = s1v; i1[r1] = tid; }
    if (r2 < 16) { v2[r2] = s2v; i2[r2] = tid; }
    __syncthreads();

    if (tid < 50) {
        int a = CAND_A[tid], b = CAND_B[tid];
        cv[tid] = v1[a] + v2[b];
        ci[tid] = i1[a] * NSUB + i2[b];
    }
    __syncthreads();
    if (tid < 50) {
        float v = cv[tid];
        int r = 0;
#pragma unroll 10
        for (int j = 0; j < 50; j++) {
            float w = cv[j];
            r += (w > v) || (w == v && j < tid);
        }
        if (r < 16) sel[r] = ci[tid];
    }
    __syncthreads();

#pragma unroll
    for (int k = 0; k < 16; k++)
        ews[k][tid] = expert_w[(size_t)sel[k] * DKEY + tid];
    __syncthreads();

    int k8 = tid >> 3, l8 = tid & 7;
    float part = 0.f;
#pragma unroll
    for (int i = 0; i < 16; i++) {
        int d = l8 * 16 + i;
        part += q[d] * ews[k8][d];
    }
    part += __shfl_down_sync(0xffffffffu, part, 4);
    part += __shfl_down_sync(0xffffffffu, part, 2);
    part += __shfl_down_sync(0xffffffffu, part, 1);
    if (l8 == 0) simv[k8] = part;
    __syncthreads();

    if (tid == 0) {
        float m = -INFINITY;
#pragma unroll
        for (int k = 0; k < 16; k++) m = fmaxf(m, simv[k]);
        float e[16]; float s = 0.f;
#pragma unroll
        for (int k = 0; k < 16; k++) { e[k] = expf(simv[k] - m); s += e[k]; }
        float inv = 1.f / s;
#pragma unroll
        for (int k = 0; k < 16; k++) rw[k] = e[k] * inv;
    }
    __syncthreads();

    float o = 0.f;
#pragma unroll
    for (int k = 0; k < 16; k++) o += rw[k] * ews[k][tid];
    size_t idx = (size_t)token * 2048 + head * 128 + tid;
    __nv_bfloat16 h = __float2bfloat16(o);
    g_cat_hi[idx] = h;
    g_cat_lo[idx] = __float2bfloat16(o - __bfloat162float(h));
}

// y = rmsnorm(x + g_sum[0] + g_sum[1]) * rms_w
__global__ void __launch_bounds__(256) final_rms(
    const float* __restrict__ x, const float* __restrict__ rms_w,
    float* __restrict__ y)
{
    int token = blockIdx.x;
    int t = threadIdx.x;
    size_t base = (size_t)token * DMODEL;
    const size_t half = (size_t)NTOK * DMODEL;
    float v[4];
    float ss = 0.f;
#pragma unroll
    for (int u = 0; u < 4; u++) {
        int c = t + u * 256;
        float s = x[base + c] + g_sum[base + c] + g_sum[half + base + c];
        v[u] = s;
        ss += s * s;
    }
#pragma unroll
    for (int off = 16; off; off >>= 1)
        ss += __shfl_xor_sync(0xffffffffu, ss, off);
    __shared__ float red[8];
    __shared__ float stot;
    if ((t & 31) == 0) red[t >> 5] = ss;
    __syncthreads();
    if (t == 0) {
        float s = 0.f;
#pragma unroll
        for (int i = 0; i < 8; i++) s += red[i];
        stot = rsqrtf(s * (1.f / DMODEL) + 1e-6f);
    }
    __syncthreads();
    float inv = stot;
#pragma unroll
    for (int u = 0; u < 4; u++) {
        int c = t + u * 256;
        y[base + c] = v[u] * inv * rms_w[c];
    }
}

// ============================================================================
extern "C" void kernel_launch(void* const* d_in, const int* in_sizes, int n_in,
                              void* d_out, int out_size)
{
    const float* x         = (const float*)d_in[0];
    const float* wq        = (const float*)d_in[1];
    const float* bq        = (const float*)d_in[2];
    const float* bn_w      = (const float*)d_in[3];
    const float* bn_b      = (const float*)d_in[4];
    const float* bn_mean   = (const float*)d_in[5];
    const float* bn_var    = (const float*)d_in[6];
    const float* sub_keys  = (const float*)d_in[7];
    const float* expert_w  = (const float*)d_in[8];
    const float* wo        = (const float*)d_in[9];
    const float* bo        = (const float*)d_in[10];
    const float* in_proj_w = (const float*)d_in[11];
    const float* in_proj_b = (const float*)d_in[12];
    const float* attn_ow   = (const float*)d_in[13];
    const float* attn_ob   = (const float*)d_in[14];
    const float* rms_w     = (const float*)d_in[15];

    float* y      = (float*)d_out;
    float* attn_w = (float*)d_out + (size_t)NTOK * DMODEL;

    void *p_qkv, *p_sum, *p_s, *p_att;
    cudaGetSymbolAddress(&p_qkv, g_qkv);
    cudaGetSymbolAddress(&p_sum, g_sum);
    cudaGetSymbolAddress(&p_s, g_s);
    cudaGetSymbolAddress(&p_att, g_att);

    void *xh, *xl, *w1h, *w1l, *w2h, *w2l, *ch, *cl, *qbh, *qbl, *bdh, *bdl;
    void *qah, *qal, *kah, *kal, *ph, *pl, *vth, *vtl;
    cudaGetSymbolAddress(&xh,  g_x_hi);  cudaGetSymbolAddress(&xl,  g_x_lo);
    cudaGetSymbolAddress(&w1h, g_w1_hi); cudaGetSymbolAddress(&w1l, g_w1_lo);
    cudaGetSymbolAddress(&w2h, g_w2_hi); cudaGetSymbolAddress(&w2l, g_w2_lo);
    cudaGetSymbolAddress(&ch,  g_cat_hi); cudaGetSymbolAddress(&cl, g_cat_lo);
    cudaGetSymbolAddress(&qbh, g_qbn_hi); cudaGetSymbolAddress(&qbl, g_qbn_lo);
    cudaGetSymbolAddress(&bdh, g_bd_hi); cudaGetSymbolAddress(&bdl, g_bd_lo);
    cudaGetSymbolAddress(&qah, g_qa_hi); cudaGetSymbolAddress(&qal, g_qa_lo);
    cudaGetSymbolAddress(&kah, g_ka_hi); cudaGetSymbolAddress(&kal, g_ka_lo);
    cudaGetSymbolAddress(&ph,  g_p_hi);  cudaGetSymbolAddress(&pl,  g_p_lo);
    cudaGetSymbolAddress(&vth, g_vt_hi); cudaGetSymbolAddress(&vtl, g_vt_lo);

    constexpr int SMEM4 = 2 * (2 * 128 * 80 + 2 * 128 * 80);  // 81920
    constexpr int SMEM2 = 2 * (2 * 64 * 80 + 2 * 128 * 80);   // 61440
    cudaFuncSetAttribute(gemm_mma<4>, cudaFuncAttributeMaxDynamicSharedMemorySize, SMEM4);
    cudaFuncSetAttribute(gemm_mma<2>, cudaFuncAttributeMaxDynamicSharedMemorySize, SMEM2);

    const float scale = 0.08838834764831845f;   // 1/sqrt(128)

    cudaEvent_t ev_fork, ev_join;
    cudaEventCreateWithFlags(&ev_fork, cudaEventDisableTiming);
    cudaEventCreateWithFlags(&ev_join, cudaEventDisableTiming);
    cudaStream_t sB = cudaStreamPerThread;

    // ---- legacy stream: split + gemm1 ----
    split_all<<<(int)((X4 + W14 + W24 + BD4) / 256), 256>>>(
        x, wq, in_proj_w, wo, attn_ow, sub_keys);

    gemm_mma<4><<<dim3(4096 / 128, NTOK / 128), 256, SMEM4>>>(
        (const __nv_bfloat16*)xh, (const __nv_bfloat16*)xl,
        (const __nv_bfloat16*)w1h, (const __nv_bfloat16*)w1l,
        DMODEL, DMODEL, 0, 0,
        bq, in_proj_b, bn_mean, bn_var, bn_w, bn_b,
        0, 1.f,
        (float*)p_qkv, 3 * DMODEL, (float*)p_qkv, 3 * DMODEL, 1024, 0, DMODEL);

    cudaEventRecord(ev_fork, 0);
    cudaStreamWaitEvent(sB, ev_fork, 0);

    // ---- stream B: PEER chain (ALU-heavy) ----
    gemm_mma<4><<<dim3(2, 64), 256, SMEM4, sB>>>(
        (const __nv_bfloat16*)qbh, (const __nv_bfloat16*)qbl,
        (const __nv_bfloat16*)bdh, (const __nv_bfloat16*)bdl,
        128, 128, 0, 0,
        nullptr, nullptr, nullptr, nullptr, nullptr, nullptr,
        2, 1.f,
        (float*)p_s, 256, (float*)p_s, 256, 1 << 30, 0, 128);

    peer_route<<<NTOK * NHEADS, 128, 0, sB>>>(expert_w);
    cudaEventRecord(ev_join, sB);

    // ---- legacy stream: attention chain (tensor/mem-heavy) ----
    gemm_mma<4><<<dim3(4, 4, NZ), 256, SMEM4>>>(
        (const __nv_bfloat16*)qah, (const __nv_bfloat16*)qal,
        (const __nv_bfloat16*)kah, (const __nv_bfloat16*)kal,
        HD, HD, (size_t)TSEQ * HD, (size_t)TSEQ * HD,
        nullptr, nullptr, nullptr, nullptr, nullptr, nullptr,
        3, scale,
        (float*)p_att, TSEQ, (float*)p_att, TSEQ, 1 << 30,
        (size_t)TSEQ * TSEQ, HD);

    attn_softmax_mean<<<NTOK, 512>>>(attn_w);

    v_transpose<<<dim3(TSEQ / 32, HD / 32, NZ), 256>>>();

    gemm_mma<2><<<dim3(1, 8, NZ), 256, SMEM2>>>(
        (const __nv_bfloat16*)ph, (const __nv_bfloat16*)pl,
        (const __nv_bfloat16*)vth, (const __nv_bfloat16*)vtl,
        TSEQ, TSEQ, (size_t)TSEQ * TSEQ, (size_t)HD * TSEQ,
        nullptr, nullptr, nullptr, nullptr, nullptr, nullptr,
        4, 1.f,
        nullptr, 0, nullptr, 0, 1 << 30, 0, TSEQ);

    // ---- join: output projection (split-K x2) + rmsnorm ----
    cudaStreamWaitEvent(0, ev_join, 0);

    gemm_mma<2><<<dim3(DMODEL / 128, NTOK / 64, 2), 256, SMEM2>>>(
        (const __nv_bfloat16*)ch, (const __nv_bfloat16*)cl,
        (const __nv_bfloat16*)w2h, (const __nv_bfloat16*)w2l,
        2048, 2048, 1024, 1024,
        bo, attn_ob, nullptr, nullptr, nullptr, nullptr,
        1, 1.f,
        (float*)p_sum, DMODEL, (float*)p_sum, DMODEL, 1 << 30,
        (size_t)NTOK * DMODEL, 1024);

    final_rms<<<NTOK, 256>>>(x, rms_w, y);

    cudaEventDestroy(ev_fork);
    cudaEventDestroy(ev_join);

    (void)in_sizes; (void)n_in; (void)out_size;
}

// round 15
// speedup vs baseline: 1.1167x; 1.0133x over previous
#include <cuda_runtime.h>
#include <cuda_bf16.h>
#include <math.h>
#include <stdint.h>

// ---------------- problem constants ----------------
#define BATCH   2
#define TSEQ    512
#define NTOK    1024
#define DMODEL  1024
#define NHEADS  8
#define DKEY    128
#define HK      1024
#define NSUB    128
#define TOPK    16
#define HD      128
#define NZ      16        // BATCH*NHEADS

// ---------------- scratch ----------------
__device__ __align__(128) float g_qkv[NTOK * 3 * DMODEL];
__device__ __align__(128) float g_att[NZ * TSEQ * TSEQ];   // raw scores
__device__ __align__(128) float g_sum[2 * NTOK * DMODEL];  // split-K partials
__device__ __align__(128) float g_s[NTOK * NHEADS * 256];

__device__ __align__(128) __nv_bfloat16 g_x_hi[NTOK * DMODEL],  g_x_lo[NTOK * DMODEL];
__device__ __align__(128) __nv_bfloat16 g_w1_hi[4096 * DMODEL], g_w1_lo[4096 * DMODEL];
__device__ __align__(128) __nv_bfloat16 g_w2_hi[DMODEL * 2048], g_w2_lo[DMODEL * 2048];
__device__ __align__(128) __nv_bfloat16 g_cat_hi[NTOK * 2048],  g_cat_lo[NTOK * 2048];
__device__ __align__(128) __nv_bfloat16 g_qbn_hi[NTOK * HK],    g_qbn_lo[NTOK * HK];
__device__ __align__(128) __nv_bfloat16 g_bd_hi[256 * 128],     g_bd_lo[256 * 128];
__device__ __align__(128) __nv_bfloat16 g_qa_hi[NZ * TSEQ * HD], g_qa_lo[NZ * TSEQ * HD];
__device__ __align__(128) __nv_bfloat16 g_ka_hi[NZ * TSEQ * HD], g_ka_lo[NZ * TSEQ * HD];
__device__ __align__(128) __nv_bfloat16 g_p_hi[NZ * TSEQ * TSEQ], g_p_lo[NZ * TSEQ * TSEQ];
__device__ __align__(128) __nv_bfloat16 g_vt_hi[NZ * HD * TSEQ],  g_vt_lo[NZ * HD * TSEQ];

// 50 candidates (a,b) with (a+1)(b+1) <= 16 over rank-sorted v1,v2
__device__ const int CAND_A[50] = {0,0,0,0,0,0,0,0,0,0,0,0,0,0,0,0,
                                   1,1,1,1,1,1,1,1, 2,2,2,2,2, 3,3,3,3,
                                   4,4,4, 5,5, 6,6, 7,7, 8,9,10,11,12,13,14,15};
__device__ const int CAND_B[50] = {0,1,2,3,4,5,6,7,8,9,10,11,12,13,14,15,
                                   0,1,2,3,4,5,6,7, 0,1,2,3,4, 0,1,2,3,
                                   0,1,2, 0,1, 0,1, 0,1, 0,0,0,0,0,0,0,0};

// ---------------- helpers ----------------
__device__ __forceinline__ uint32_t smem_u32(const void* p) {
    uint32_t a;
    asm("{ .reg .u64 t; cvta.to.shared.u64 t, %1; cvt.u32.u64 %0, t; }"
        : "=r"(a) : "l"(p));
    return a;
}
#define LDSM4(r, addr) \
    asm volatile("ldmatrix.sync.aligned.m8n8.x4.shared.b16 {%0,%1,%2,%3}, [%4];" \
        : "=r"((r)[0]), "=r"((r)[1]), "=r"((r)[2]), "=r"((r)[3]) : "r"(addr))
#define MMA_BF16(d, a, b0, b1) \
    asm volatile("mma.sync.aligned.m16n8k16.row.col.f32.bf16.bf16.f32 " \
        "{%0,%1,%2,%3}, {%4,%5,%6,%7}, {%8,%9}, {%0,%1,%2,%3};" \
        : "+f"((d)[0]), "+f"((d)[1]), "+f"((d)[2]), "+f"((d)[3]) \
        : "r"((a)[0]), "r"((a)[1]), "r"((a)[2]), "r"((a)[3]), "r"(b0), "r"(b1))
#define CP16(dst, src) \
    asm volatile("cp.async.cg.shared.global [%0], [%1], 16;" :: "r"(dst), "l"(src))
#define CP_COMMIT() asm volatile("cp.async.commit_group;" ::: "memory")
#define CP_WAIT0()  asm volatile("cp.async.wait_group 0;" ::: "memory")

__device__ __forceinline__ void bf16x2_split_store(__nv_bfloat16* hi, __nv_bfloat16* lo,
                                                   size_t idx, float a, float b) {
    __nv_bfloat16 h0 = __float2bfloat16(a);
    __nv_bfloat16 h1 = __float2bfloat16(b);
    *(__nv_bfloat162*)(hi + idx) = __nv_bfloat162(h0, h1);
    *(__nv_bfloat162*)(lo + idx) = __nv_bfloat162(
        __float2bfloat16(a - __bfloat162float(h0)),
        __float2bfloat16(b - __bfloat162float(h1)));
}

// monotone uint mapping of float (order-preserving)
__device__ __forceinline__ uint32_t fmono(float f) {
    uint32_t b = __float_as_uint(f);
    return b ^ (uint32_t)(((int32_t)b >> 31) | 0x80000000);
}

// ============================================================================
// combined split kernel
// ============================================================================
__device__ __forceinline__ void split_store4(float4 v, __nv_bfloat16* hi,
                                             __nv_bfloat16* lo, size_t i4) {
    float vv[4] = {v.x, v.y, v.z, v.w};
    __nv_bfloat16 h[4], l[4];
#pragma unroll
    for (int k = 0; k < 4; k++) {
        h[k] = __float2bfloat16(vv[k]);
        l[k] = __float2bfloat16(vv[k] - __bfloat162float(h[k]));
    }
    ((__nv_bfloat162*)hi)[2 * i4]     = __nv_bfloat162(h[0], h[1]);
    ((__nv_bfloat162*)hi)[2 * i4 + 1] = __nv_bfloat162(h[2], h[3]);
    ((__nv_bfloat162*)lo)[2 * i4]     = __nv_bfloat162(l[0], l[1]);
    ((__nv_bfloat162*)lo)[2 * i4 + 1] = __nv_bfloat162(l[2], l[3]);
}

#define X4   ((size_t)NTOK * DMODEL / 4)
#define W14  ((size_t)4096 * DMODEL / 4)
#define W24  ((size_t)DMODEL * 2048 / 4)
#define BD4  ((size_t)256 * 128 / 4)

__global__ void __launch_bounds__(256) split_all(
    const float* __restrict__ x,  const float* __restrict__ wq,
    const float* __restrict__ ipw, const float* __restrict__ wo,
    const float* __restrict__ aow, const float* __restrict__ sub_keys)
{
    size_t i = (size_t)blockIdx.x * 256 + threadIdx.x;
    if (i < X4) {
        split_store4(((const float4*)x)[i], g_x_hi, g_x_lo, i);
    } else if (i < X4 + W14) {
        size_t j = i - X4;
        const size_t cut = (size_t)1024 * 1024 / 4;
        float4 v = (j < cut) ? ((const float4*)wq)[j] : ((const float4*)ipw)[j - cut];
        split_store4(v, g_w1_hi, g_w1_lo, j);
    } else if (i < X4 + W14 + W24) {
        size_t j = i - X4 - W14;
        int row = (int)(j >> 9);
        int c4  = (int)(j & 511);
        float4 v = (c4 < 256) ? ((const float4*)wo)[row * 256 + c4]
                              : ((const float4*)aow)[row * 256 + c4 - 256];
        split_store4(v, g_w2_hi, g_w2_lo, j);
    } else {
        size_t j = i - X4 - W14 - W24;
        int row = (int)(j >> 5);
        int c4  = (int)(j & 31);
        float4 v = make_float4(0.f, 0.f, 0.f, 0.f);
        if (row < 128 && c4 < 16)
            v = ((const float4*)sub_keys)[row * 16 + c4];
        else if (row >= 128 && c4 >= 16)
            v = ((const float4*)(sub_keys + 128 * 64))[(row - 128) * 16 + (c4 - 16)];
        split_store4(v, g_bd_hi, g_bd_lo, j);
    }
}

// ============================================================================
// bf16-split "3M" GEMM
// ============================================================================
template<int MT>
__global__ void __launch_bounds__(256, 2) gemm_mma(
    const __nv_bfloat16* __restrict__ Ahi, const __nv_bfloat16* __restrict__ Alo,
    const __nv_bfloat16* __restrict__ Bhi, const __nv_bfloat16* __restrict__ Blo,
    int lda, int ldb, size_t batchA, size_t batchB,
    const float* __restrict__ biasA, const float* __restrict__ biasB,
    const float* __restrict__ bn_mean, const float* __restrict__ bn_var,
    const float* __restrict__ bn_w, const float* __restrict__ bn_b,
    int mode, float scale,
    float* __restrict__ C0, int ld0, float* __restrict__ C1, int ld1, int ncut,
    size_t batchC, int K)
{
    constexpr int CM   = 32 * MT;
    constexpr int A_T  = CM * 80;
    constexpr int B_T  = 128 * 80;
    constexpr int STG  = 2 * A_T + 2 * B_T;

    extern __shared__ char smc[];
    uint32_t base = smem_u32(smc);
    int t = threadIdx.x, warp = t >> 5, lane = t & 31;
    int m0 = blockIdx.y * CM, n0 = blockIdx.x * 128;
    int z  = blockIdx.z;
    int wm = warp >> 2, wn = warp & 3;

    const __nv_bfloat16* Ah = Ahi + batchA * z;
    const __nv_bfloat16* Al = Alo + batchA * z;
    const __nv_bfloat16* Bh = Bhi + batchB * z;
    const __nv_bfloat16* Bl = Blo + batchB * z;

    float acc[MT][4][4];
#pragma unroll
    for (int i = 0; i < MT; i++)
#pragma unroll
        for (int j = 0; j < 4; j++)
#pragma unroll
            for (int r = 0; r < 4; r++) acc[i][j][r] = 0.f;

    const int niter = K >> 5;

    auto issue = [&](int it) {
        uint32_t sb = base + (it & 1) * STG;
        int k0 = it << 5;
#pragma unroll
        for (int p = 0; p < CM / 64; p++) {
            int c = t + p * 256;
            int row = c >> 2, j = c & 3;
            const __nv_bfloat16* sh = Ah + (size_t)(m0 + row) * lda + k0 + j * 8;
            const __nv_bfloat16* sl = Al + (size_t)(m0 + row) * lda + k0 + j * 8;
            uint32_t d = sb + (uint32_t)(row * 80 + j * 16);
            CP16(d, sh);
            CP16(d + A_T, sl);
        }
#pragma unroll
        for (int p = 0; p < 2; p++) {
            int c = t + p * 256;
            int row = c >> 2, j = c & 3;
            const __nv_bfloat16* sh = Bh + (size_t)(n0 + row) * ldb + k0 + j * 8;
            const __nv_bfloat16* sl = Bl + (size_t)(n0 + row) * ldb + k0 + j * 8;
            uint32_t d = sb + 2 * A_T + (uint32_t)(row * 80 + j * 16);
            CP16(d, sh);
            CP16(d + B_T, sl);
        }
    };

    issue(0); CP_COMMIT();

    uint32_t a_off = (uint32_t)((wm * (16 * MT) + (lane & 15)) * 80 + (lane >> 4) * 16);
    uint32_t b_off = (uint32_t)((wn * 32 + (lane & 15)) * 80 + (lane >> 4) * 16);

    for (int it = 0; it < niter; ++it) {
        CP_WAIT0();
        __syncthreads();
        if (it + 1 < niter) { issue(it + 1); CP_COMMIT(); }

        uint32_t sb = base + (it & 1) * STG;
        uint32_t sa_h = sb, sa_l = sb + A_T;
        uint32_t sb_h = sb + 2 * A_T, sb_l = sb + 2 * A_T + B_T;

#pragma unroll
        for (int ks = 0; ks < 2; ks++) {
            uint32_t kb = ks * 32;
            uint32_t ah[MT][4], al[MT][4], bh[2][4], bl[2][4];
#pragma unroll
            for (int mt = 0; mt < MT; mt++) {
                uint32_t o = a_off + mt * 16 * 80 + kb;
                LDSM4(ah[mt], sa_h + o);
                LDSM4(al[mt], sa_l + o);
            }
#pragma unroll
            for (int bt = 0; bt < 2; bt++) {
                uint32_t o = b_off + bt * 16 * 80 + kb;
                LDSM4(bh[bt], sb_h + o);
                LDSM4(bl[bt], sb_l + o);
            }
#pragma unroll
            for (int mt = 0; mt < MT; mt++)
#pragma unroll
                for (int nt = 0; nt < 4; nt++)
                    MMA_BF16(acc[mt][nt], ah[mt], bh[nt >> 1][nt & 1], bh[nt >> 1][(nt & 1) + 2]);
#pragma unroll
            for (int mt = 0; mt < MT; mt++)
#pragma unroll
                for (int nt = 0; nt < 4; nt++)
                    MMA_BF16(acc[mt][nt], al[mt], bh[nt >> 1][nt & 1], bh[nt >> 1][(nt & 1) + 2]);
#pragma unroll
            for (int mt = 0; mt < MT; mt++)
#pragma unroll
                for (int nt = 0; nt < 4; nt++)
                    MMA_BF16(acc[mt][nt], ah[mt], bl[nt >> 1][nt & 1], bl[nt >> 1][(nt & 1) + 2]);
        }
    }

    // ---- epilogue ----
    int g = lane >> 2, c2 = lane & 3;
#pragma unroll
    for (int mt = 0; mt < MT; mt++) {
#pragma unroll
        for (int nt = 0; nt < 4; nt++) {
            int row = m0 + wm * (16 * MT) + mt * 16 + g;
            int col = n0 + wn * 32 + nt * 8 + 2 * c2;
            float v[4] = {acc[mt][nt][0], acc[mt][nt][1], acc[mt][nt][2], acc[mt][nt][3]};
            if (mode == 4) {
#pragma unroll
                for (int rr = 0; rr < 2; rr++) {
                    size_t idx = (size_t)((z >> 3) * 512 + row + rr * 8) * 2048
                               + 1024 + (z & 7) * 128 + col;
                    bf16x2_split_store(g_cat_hi, g_cat_lo, idx, v[2 * rr], v[2 * rr + 1]);
                }
                continue;
            }
            if (mode == 3) {
                v[0] *= scale; v[1] *= scale; v[2] *= scale; v[3] *= scale;
            } else if (mode == 0) {
                if (col < 1024) {
                    float sc0 = rsqrtf(bn_var[col] + 1e-5f) * bn_w[col];
                    float sc1 = rsqrtf(bn_var[col + 1] + 1e-5f) * bn_w[col + 1];
                    float of0 = (biasA[col] - bn_mean[col]) * sc0 + bn_b[col];
                    float of1 = (biasA[col + 1] - bn_mean[col + 1]) * sc1 + bn_b[col + 1];
                    v[0] = v[0] * sc0 + of0; v[1] = v[1] * sc1 + of1;
                    v[2] = v[2] * sc0 + of0; v[3] = v[3] * sc1 + of1;
#pragma unroll
                    for (int rr = 0; rr < 2; rr++)
                        bf16x2_split_store(g_qbn_hi, g_qbn_lo,
                                           (size_t)(row + rr * 8) * 1024 + col,
                                           v[2 * rr], v[2 * rr + 1]);
                    continue;
                }
                float b0 = biasB[col - 1024], b1 = biasB[col + 1 - 1024];
                v[0] += b0; v[1] += b1; v[2] += b0; v[3] += b1;
                if (col < 3072) {
                    // qa/ka: bf16 per-head only — fp32 qkv store is dead, skip it
                    int cc   = (col < 2048) ? col - 1024 : col - 2048;
                    int h    = cc >> 7, d = cc & 127;
                    __nv_bfloat16* oh = (col < 2048) ? g_qa_hi : g_ka_hi;
                    __nv_bfloat16* ol = (col < 2048) ? g_qa_lo : g_ka_lo;
#pragma unroll
                    for (int rr = 0; rr < 2; rr++) {
                        int token = row + rr * 8;
                        int zz = (token >> 9) * 8 + h;
                        size_t idx = (size_t)zz * (TSEQ * HD)
                                   + (size_t)(token & 511) * HD + d;
                        bf16x2_split_store(oh, ol, idx, v[2 * rr], v[2 * rr + 1]);
                    }
                    continue;
                }
            } else if (mode == 1) {
                if (z == 0) {
                    float b0 = biasA[col] + biasB[col];
                    float b1 = biasA[col + 1] + biasB[col + 1];
                    v[0] += b0; v[1] += b1; v[2] += b0; v[3] += b1;
                }
            }
            float* C; int ld, cc;
            if (col < ncut) { C = C0; ld = ld0; cc = col; }
            else            { C = C1; ld = ld1; cc = col - ncut; }
            C += batchC * z;
            *(float2*)(C + (size_t)row * ld + cc)       = make_float2(v[0], v[1]);
            *(float2*)(C + (size_t)(row + 8) * ld + cc) = make_float2(v[2], v[3]);
        }
    }
}

// ============================================================================
// fused softmax + head-mean + P bf16 split
// ============================================================================
__global__ void __launch_bounds__(512) attn_softmax_mean(float* __restrict__ attn_w)
{
    int bq = blockIdx.x;
    int b  = bq >> 9, qi = bq & 511;
    int t  = threadIdx.x;
    int g  = t >> 6;
    int u  = t & 63;
    int w  = t >> 5;

    __shared__ float sp[8][512];
    __shared__ float red[32];

    int z = b * 8 + g;
    const float* arow = g_att + ((size_t)z * TSEQ + qi) * TSEQ;

    float v[8];
    float mx = -INFINITY;
#pragma unroll
    for (int i = 0; i < 8; i++) {
        v[i] = arow[u + i * 64];
        mx = fmaxf(mx, v[i]);
    }
#pragma unroll
    for (int off = 16; off; off >>= 1)
        mx = fmaxf(mx, __shfl_xor_sync(0xffffffffu, mx, off));
    if ((t & 31) == 0) red[w] = mx;
    __syncthreads();
    float hm = fmaxf(red[2 * g], red[2 * g + 1]);

    float e[8], s = 0.f;
#pragma unroll
    for (int i = 0; i < 8; i++) { e[i] = expf(v[i] - hm); s += e[i]; }
#pragma unroll
    for (int off = 16; off; off >>= 1)
        s += __shfl_xor_sync(0xffffffffu, s, off);
    if ((t & 31) == 0) red[16 + w] = s;
    __syncthreads();
    float inv = 1.f / (red[16 + 2 * g] + red[16 + 2 * g + 1]);

    size_t pbase = ((size_t)z * TSEQ + qi) * TSEQ;
#pragma unroll
    for (int i = 0; i < 8; i++) {
        float p = e[i] * inv;
        int k = u + i * 64;
        sp[g][k] = p;
        __nv_bfloat16 h = __float2bfloat16(p);
        g_p_hi[pbase + k] = h;
        g_p_lo[pbase + k] = __float2bfloat16(p - __bfloat162float(h));
    }
    __syncthreads();

    float m8 = 0.f;
#pragma unroll
    for (int h = 0; h < 8; h++) m8 += sp[h][t];
    attn_w[(size_t)bq * TSEQ + t] = m8 * 0.125f;
}

// ============================================================================
// V transpose
// ============================================================================
__global__ void __launch_bounds__(256) v_transpose()
{
    int z = blockIdx.z;
    int b = z >> 3, h = z & 7;
    int k0 = blockIdx.x * 32, e0 = blockIdx.y * 32;
    __shared__ float tile[32][33];
    int tx = threadIdx.x & 31, ty = threadIdx.x >> 5;

#pragma unroll
    for (int s = 0; s < 4; s++) {
        int k = k0 + ty + s * 8;
        tile[ty + s * 8][tx] =
            g_qkv[(size_t)(b * TSEQ + k) * (3 * DMODEL) + 2 * DMODEL + h * HD + e0 + tx];
    }
    __syncthreads();
#pragma unroll
    for (int s = 0; s < 4; s++) {
        int e = e0 + ty + s * 8;
        float v = tile[tx][ty + s * 8];
        size_t idx = (size_t)z * (HD * TSEQ) + (size_t)e * TSEQ + k0 + tx;
        __nv_bfloat16 hh = __float2bfloat16(v);
        g_vt_hi[idx] = hh;
        g_vt_lo[idx] = __float2bfloat16(v - __bfloat162float(hh));
    }
}

// ============================================================================
// PEER routing: u64 monotone keys, LDS.128 (2 keys/load) rank loop
// ============================================================================
__global__ void __launch_bounds__(128) peer_route(const float* __restrict__ expert_w)
{
    int row   = blockIdx.x;
    int token = row >> 3;
    int head  = row & 7;
    int tid   = threadIdx.x;

    __shared__ float q[128];
    __shared__ __align__(16) unsigned long long k1s[128], k2s[128];
    __shared__ float v1[16], v2[16];
    __shared__ int   i1[16], i2[16];
    __shared__ float cv[50];
    __shared__ int   ci[50];
    __shared__ int   sel[16];
    __shared__ float simv[16];
    __shared__ float rw[16];
    __shared__ float ews[16][128];

    size_t qidx = (size_t)token * HK + head * 128 + tid;
    q[tid] = __bfloat162float(g_qbn_hi[qidx]) + __bfloat162float(g_qbn_lo[qidx]);
    float s1v = g_s[(size_t)row * 256 + tid];
    float s2v = g_s[(size_t)row * 256 + 128 + tid];
    unsigned long long myk1 = ((unsigned long long)fmono(s1v) << 7) | (unsigned long long)(127 - tid);
    unsigned long long myk2 = ((unsigned long long)fmono(s2v) << 7) | (unsigned long long)(127 - tid);
    k1s[tid] = myk1;
    k2s[tid] = myk2;
    __syncthreads();

    int r1 = 0, r2 = 0;
    const ulonglong2* k1v = (const ulonglong2*)k1s;
    const ulonglong2* k2v = (const ulonglong2*)k2s;
#pragma unroll 16
    for (int j = 0; j < 64; j++) {
        ulonglong2 a = k1v[j];
        ulonglong2 b = k2v[j];
        r1 += (a.x > myk1) + (a.y > myk1);
        r2 += (b.x > myk2) + (b.y > myk2);
    }
    if (r1 < 16) { v1[r1] = s1v; i1[r1] = tid; }
    if (r2 < 16) { v2[r2] = s2v; i2[r2] = tid; }
    __syncthreads();

    if (tid < 50) {
        int a = CAND_A[tid], b = CAND_B[tid];
        cv[tid] = v1[a] + v2[b];
        ci[tid] = i1[a] * NSUB + i2[b];
    }
    __syncthreads();
    if (tid < 50) {
        float v = cv[tid];
        int r = 0;
#pragma unroll 10
        for (int j = 0; j < 50; j++) {
            float w = cv[j];
            r += (w > v) || (w == v && j < tid);
        }
        if (r < 16) sel[r] = ci[tid];
    }
    __syncthreads();

#pragma unroll
    for (int k = 0; k < 16; k++)
        ews[k][tid] = expert_w[(size_t)sel[k] * DKEY + tid];
    __syncthreads();

    int k8 = tid >> 3, l8 = tid & 7;
    float part = 0.f;
#pragma unroll
    for (int i = 0; i < 16; i++) {
        int d = l8 * 16 + i;
        part += q[d] * ews[k8][d];
    }
    part += __shfl_down_sync(0xffffffffu, part, 4);
    part += __shfl_down_sync(0xffffffffu, part, 2);
    part += __shfl_down_sync(0xffffffffu, part, 1);
    if (l8 == 0) simv[k8] = part;
    __syncthreads();

    if (tid == 0) {
        float m = -INFINITY;
#pragma unroll
        for (int k = 0; k < 16; k++) m = fmaxf(m, simv[k]);
        float e[16]; float s = 0.f;
#pragma unroll
        for (int k = 0; k < 16; k++) { e[k] = expf(simv[k] - m); s += e[k]; }
        float inv = 1.f / s;
#pragma unroll
        for (int k = 0; k < 16; k++) rw[k] = e[k] * inv;
    }
    __syncthreads();

    float o = 0.f;
#pragma unroll
    for (int k = 0; k < 16; k++) o += rw[k] * ews[k][tid];
    size_t idx = (size_t)token * 2048 + head * 128 + tid;
    __nv_bfloat16 h = __float2bfloat16(o);
    g_cat_hi[idx] = h;
    g_cat_lo[idx] = __float2bfloat16(o - __bfloat162float(h));
}

// y = rmsnorm(x + g_sum[0] + g_sum[1]) * rms_w
__global__ void __launch_bounds__(256) final_rms(
    const float* __restrict__ x, const float* __restrict__ rms_w,
    float* __restrict__ y)
{
    int token = blockIdx.x;
    int t = threadIdx.x;
    size_t base = (size_t)token * DMODEL;
    const size_t half = (size_t)NTOK * DMODEL;
    float v[4];
    float ss = 0.f;
#pragma unroll
    for (int u = 0; u < 4; u++) {
        int c = t + u * 256;
        float s = x[base + c] + g_sum[base + c] + g_sum[half + base + c];
        v[u] = s;
        ss += s * s;
    }
#pragma unroll
    for (int off = 16; off; off >>= 1)
        ss += __shfl_xor_sync(0xffffffffu, ss, off);
    __shared__ float red[8];
    __shared__ float stot;
    if ((t & 31) == 0) red[t >> 5] = ss;
    __syncthreads();
    if (t == 0) {
        float s = 0.f;
#pragma unroll
        for (int i = 0; i < 8; i++) s += red[i];
        stot = rsqrtf(s * (1.f / DMODEL) + 1e-6f);
    }
    __syncthreads();
    float inv = stot;
#pragma unroll
    for (int u = 0; u < 4; u++) {
        int c = t + u * 256;
        y[base + c] = v[u] * inv * rms_w[c];
    }
}

// ============================================================================
extern "C" void kernel_launch(void* const* d_in, const int* in_sizes, int n_in,
                              void* d_out, int out_size)
{
    const float* x         = (const float*)d_in[0];
    const float* wq        = (const float*)d_in[1];
    const float* bq        = (const float*)d_in[2];
    const float* bn_w      = (const float*)d_in[3];
    const float* bn_b      = (const float*)d_in[4];
    const float* bn_mean   = (const float*)d_in[5];
    const float* bn_var    = (const float*)d_in[6];
    const float* sub_keys  = (const float*)d_in[7];
    const float* expert_w  = (const float*)d_in[8];
    const float* wo        = (const float*)d_in[9];
    const float* bo        = (const float*)d_in[10];
    const float* in_proj_w = (const float*)d_in[11];
    const float* in_proj_b = (const float*)d_in[12];
    const float* attn_ow   = (const float*)d_in[13];
    const float* attn_ob   = (const float*)d_in[14];
    const float* rms_w     = (const float*)d_in[15];

    float* y      = (float*)d_out;
    float* attn_w = (float*)d_out + (size_t)NTOK * DMODEL;

    void *p_qkv, *p_sum, *p_s, *p_att;
    cudaGetSymbolAddress(&p_qkv, g_qkv);
    cudaGetSymbolAddress(&p_sum, g_sum);
    cudaGetSymbolAddress(&p_s, g_s);
    cudaGetSymbolAddress(&p_att, g_att);

    void *xh, *xl, *w1h, *w1l, *w2h, *w2l, *ch, *cl, *qbh, *qbl, *bdh, *bdl;
    void *qah, *qal, *kah, *kal, *ph, *pl, *vth, *vtl;
    cudaGetSymbolAddress(&xh,  g_x_hi);  cudaGetSymbolAddress(&xl,  g_x_lo);
    cudaGetSymbolAddress(&w1h, g_w1_hi); cudaGetSymbolAddress(&w1l, g_w1_lo);
    cudaGetSymbolAddress(&w2h, g_w2_hi); cudaGetSymbolAddress(&w2l, g_w2_lo);
    cudaGetSymbolAddress(&ch,  g_cat_hi); cudaGetSymbolAddress(&cl, g_cat_lo);
    cudaGetSymbolAddress(&qbh, g_qbn_hi); cudaGetSymbolAddress(&qbl, g_qbn_lo);
    cudaGetSymbolAddress(&bdh, g_bd_hi); cudaGetSymbolAddress(&bdl, g_bd_lo);
    cudaGetSymbolAddress(&qah, g_qa_hi); cudaGetSymbolAddress(&qal, g_qa_lo);
    cudaGetSymbolAddress(&kah, g_ka_hi); cudaGetSymbolAddress(&kal, g_ka_lo);
    cudaGetSymbolAddress(&ph,  g_p_hi);  cudaGetSymbolAddress(&pl,  g_p_lo);
    cudaGetSymbolAddress(&vth, g_vt_hi); cudaGetSymbolAddress(&vtl, g_vt_lo);

    constexpr int SMEM4 = 2 * (2 * 128 * 80 + 2 * 128 * 80);  // 81920
    constexpr int SMEM2 = 2 * (2 * 64 * 80 + 2 * 128 * 80);   // 61440
    cudaFuncSetAttribute(gemm_mma<4>, cudaFuncAttributeMaxDynamicSharedMemorySize, SMEM4);
    cudaFuncSetAttribute(gemm_mma<2>, cudaFuncAttributeMaxDynamicSharedMemorySize, SMEM2);

    const float scale = 0.08838834764831845f;   // 1/sqrt(128)

    cudaEvent_t ev_fork, ev_join;
    cudaEventCreateWithFlags(&ev_fork, cudaEventDisableTiming);
    cudaEventCreateWithFlags(&ev_join, cudaEventDisableTiming);
    cudaStream_t sB = cudaStreamPerThread;

    // ---- legacy stream: split + gemm1 + subkey GEMM ----
    split_all<<<(int)((X4 + W14 + W24 + BD4) / 256), 256>>>(
        x, wq, in_proj_w, wo, attn_ow, sub_keys);

    gemm_mma<4><<<dim3(4096 / 128, NTOK / 128), 256, SMEM4>>>(
        (const __nv_bfloat16*)xh, (const __nv_bfloat16*)xl,
        (const __nv_bfloat16*)w1h, (const __nv_bfloat16*)w1l,
        DMODEL, DMODEL, 0, 0,
        bq, in_proj_b, bn_mean, bn_var, bn_w, bn_b,
        0, 1.f,
        (float*)p_qkv, 3 * DMODEL, (float*)p_qkv, 3 * DMODEL, 1024, 0, DMODEL);

    gemm_mma<4><<<dim3(2, 64), 256, SMEM4>>>(
        (const __nv_bfloat16*)qbh, (const __nv_bfloat16*)qbl,
        (const __nv_bfloat16*)bdh, (const __nv_bfloat16*)bdl,
        128, 128, 0, 0,
        nullptr, nullptr, nullptr, nullptr, nullptr, nullptr,
        2, 1.f,
        (float*)p_s, 256, (float*)p_s, 256, 1 << 30, 0, 128);

    cudaEventRecord(ev_fork, 0);
    cudaStreamWaitEvent(sB, ev_fork, 0);

    // ---- stream B: peer_route only (ALU-heavy, ~62us) ----
    peer_route<<<NTOK * NHEADS, 128, 0, sB>>>(expert_w);
    cudaEventRecord(ev_join, sB);

    // ---- legacy stream: attention chain (~52us) ----
    gemm_mma<4><<<dim3(4, 4, NZ), 256, SMEM4>>>(
        (const __nv_bfloat16*)qah, (const __nv_bfloat16*)qal,
        (const __nv_bfloat16*)kah, (const __nv_bfloat16*)kal,
        HD, HD, (size_t)TSEQ * HD, (size_t)TSEQ * HD,
        nullptr, nullptr, nullptr, nullptr, nullptr, nullptr,
        3, scale,
        (float*)p_att, TSEQ, (float*)p_att, TSEQ, 1 << 30,
        (size_t)TSEQ * TSEQ, HD);

    attn_softmax_mean<<<NTOK, 512>>>(attn_w);

    v_transpose<<<dim3(TSEQ / 32, HD / 32, NZ), 256>>>();

    gemm_mma<2><<<dim3(1, 8, NZ), 256, SMEM2>>>(
        (const __nv_bfloat16*)ph, (const __nv_bfloat16*)pl,
        (const __nv_bfloat16*)vth, (const __nv_bfloat16*)vtl,
        TSEQ, TSEQ, (size_t)TSEQ * TSEQ, (size_t)HD * TSEQ,
        nullptr, nullptr, nullptr, nullptr, nullptr, nullptr,
        4, 1.f,
        nullptr, 0, nullptr, 0, 1 << 30, 0, TSEQ);

    // ---- join: output projection (split-K x2) + rmsnorm ----
    cudaStreamWaitEvent(0, ev_join, 0);

    gemm_mma<2><<<dim3(DMODEL / 128, NTOK / 64, 2), 256, SMEM2>>>(
        (const __nv_bfloat16*)ch, (const __nv_bfloat16*)cl,
        (const __nv_bfloat16*)w2h, (const __nv_bfloat16*)w2l,
        2048, 2048, 1024, 1024,
        bo, attn_ob, nullptr, nullptr, nullptr, nullptr,
        1, 1.f,
        (float*)p_sum, DMODEL, (float*)p_sum, DMODEL, 1 << 30,
        (size_t)NTOK * DMODEL, 1024);

    final_rms<<<NTOK, 256>>>(x, rms_w, y);

    cudaEventDestroy(ev_fork);
    cudaEventDestroy(ev_join);

    (void)in_sizes; (void)n_in; (void)out_size;
}